// round 13
// baseline (speedup 1.0000x reference)
#include <cuda_runtime.h>
#include <math.h>

#define BB 8
#define NN 1024
#define BN (BB*NN)
#define KNN 20
#define NEG 0.2f
#define EPS 1e-5f
#define FULLM 0xffffffffu
#define HB 4                      // half-batch (z-slices) for score/topk pipelining

// weight regions inside g_Wc
#define WS1 0        // stacked w1: 128 x 3   (384)
#define WS2 512      // stacked w2: 128 x 64  (8192)
#define WS3 9216     // stacked w3: 256 x 64  (16384)
#define WS4 26112    // diff   w4: 256 x 128  (32768)  end=58880

// -------- scratch (device globals; no allocation allowed) --------
__device__ float g_yT[BN*128];        // y transposed (B,M,128)
__device__ float g_ynT[BN*128];       // y normalized transposed
__device__ float g_XCAT[BN*512];      // concat of x1|x2|x3|x4 per point
__device__ float g_S[BB*NN*NN];       // score matrices (32MB); reused as Mx
__device__ float g_P[BN*512];         // PQ scratch
__device__ float g_P5[BN*512];        // stage5 pre-BN output (split-K accumulator)
__device__ float g_Q[BN*256];         // stage4 gathered operand (yT @ w4)
__device__ float g_Wc[64*1024];       // all prepped weights
__device__ int   g_idx[BN*KNN];       // knn indices
__device__ float g_part[2*512*512];   // BN partial sums
__device__ float g_mean[512];
__device__ float g_istd[512];

// -------- f32x2 packed helpers --------
__device__ __forceinline__ unsigned long long pack2(float x, float y) {
    unsigned long long r;
    asm("mov.b64 %0, {%1, %2};" : "=l"(r) : "f"(x), "f"(y));
    return r;
}
__device__ __forceinline__ void unpack2(unsigned long long v, float& x, float& y) {
    asm("mov.b64 {%0, %1}, %2;" : "=f"(x), "=f"(y) : "l"(v));
}
__device__ __forceinline__ void ffma2(unsigned long long& d,
                                      unsigned long long a, unsigned long long b) {
    asm("fma.rn.f32x2 %0, %1, %2, %0;" : "+l"(d) : "l"(a), "l"(b));
}

// -------- small prep kernels --------
__global__ void prep_y(const float* __restrict__ y, float* __restrict__ yT,
                       float* __restrict__ ynT) {
    int m = blockIdx.x;            // global point 0..8191
    int b = m >> 10, mm = m & 1023;
    int c = threadIdx.x;           // 128
    float v = y[((size_t)b*128 + c)*NN + mm];
    __shared__ float red[128];
    red[c] = v*v;
    __syncthreads();
    for (int s = 64; s > 0; s >>= 1) {
        if (c < s) red[c] += red[c+s];
        __syncthreads();
    }
    float nrm = sqrtf(red[0]);
    float sc = 1.0f / fmaxf(nrm, 1e-12f);
    yT [(size_t)m*128 + c] = v;
    ynT[(size_t)m*128 + c] = v * sc;
}

// one kernel prepping all weights
__global__ void make_weights(const float* __restrict__ w1, const float* __restrict__ w2,
                             const float* __restrict__ w3, const float* __restrict__ w4,
                             float* __restrict__ out) {
    int e = blockIdx.x*blockDim.x + threadIdx.x;
    if (e < 384) {
        int r = e / 3, c = e % 3;
        float v = (r < 64) ? w1[r*6 + c]
                           : w1[(r-64)*6 + 3 + c] - w1[(r-64)*6 + c];
        out[WS1 + e] = v;
    }
    int e2 = e - 384;
    if (e2 >= 0 && e2 < 8192) {
        int r = e2 >> 6, c = e2 & 63;
        float v = (r < 64) ? w2[r*128 + c]
                           : w2[(r-64)*128 + 64 + c] - w2[(r-64)*128 + c];
        out[WS2 + e2] = v;
    }
    int e3 = e2 - 8192;
    if (e3 >= 0 && e3 < 16384) {
        int r = e3 >> 6, c = e3 & 63;
        float v = (r < 128) ? w3[r*128 + c]
                            : w3[(r-128)*128 + 64 + c] - w3[(r-128)*128 + c];
        out[WS3 + e3] = v;
    }
    int e4 = e3 - 16384;
    if (e4 >= 0 && e4 < 32768) {
        int r = e4 >> 7, c = e4 & 127;
        out[WS4 + e4] = w4[r*256 + 128 + c] - w4[r*256 + c];
    }
}

// -------- stage-1 PQ: P[r][c] = sum_{k<3} x[b,k,n] * Wc1[c][k] -------------
__global__ void __launch_bounds__(256)
pq1_kernel(const float* __restrict__ x, const float* __restrict__ Wc,
           float* __restrict__ P) {
    __shared__ float w[384];
    for (int e = threadIdx.x; e < 384; e += 256) w[e] = Wc[WS1 + e];
    __syncthreads();
    int t = blockIdx.x*256 + threadIdx.x;
    int r = t >> 5;
    int cq = (t & 31) * 4;
    int b = r >> 10, n = r & 1023;
    float a0 = x[((size_t)b*3 + 0)*NN + n];
    float a1 = x[((size_t)b*3 + 1)*NN + n];
    float a2 = x[((size_t)b*3 + 2)*NN + n];
    float4 o;
    o.x = fmaf(a2, w[(cq+0)*3+2], fmaf(a1, w[(cq+0)*3+1], fmaf(a0, w[(cq+0)*3+0], 0.f)));
    o.y = fmaf(a2, w[(cq+1)*3+2], fmaf(a1, w[(cq+1)*3+1], fmaf(a0, w[(cq+1)*3+0], 0.f)));
    o.z = fmaf(a2, w[(cq+2)*3+2], fmaf(a1, w[(cq+2)*3+1], fmaf(a0, w[(cq+2)*3+0], 0.f)));
    o.w = fmaf(a2, w[(cq+3)*3+2], fmaf(a1, w[(cq+3)*3+1], fmaf(a0, w[(cq+3)*3+0], 0.f)));
    *(float4*)&P[(size_t)r*128 + cq] = o;
}

// -------- GEMM: C[r][c] (+)= sum_k A[r][k]*B[c][k] (+ selfbias) --------------
__global__ void __launch_bounds__(256, 2)
gemm128(int K, int vec, int selfbias, int accum,
        const float* __restrict__ A, int lda, int sA,
        const float* __restrict__ Bm, int ldb, int sB,
        float* __restrict__ C, int ldc, int sC) {
    __shared__ __align__(16) float As[2][16][132];
    __shared__ __align__(16) float Bs[2][16][132];
    int z = blockIdx.z;
    A  += (size_t)z * sA;
    Bm += (size_t)z * sB;
    C  += (size_t)z * sC;
    int row0 = blockIdx.y * 128, col0 = blockIdx.x * 128;
    int tid = threadIdx.x;
    int ty = tid >> 4, tx = tid & 15;

    unsigned long long acc[8][4];
    #pragma unroll
    for (int i = 0; i < 8; i++)
        #pragma unroll
        for (int j = 0; j < 4; j++) acc[i][j] = 0ULL;
    unsigned long long sq[4] = {0ULL, 0ULL, 0ULL, 0ULL};

    int nt = (K + 15) / 16;
    float ra[8], rb[8];
    float4 ra4[2], rb4[2];
    int vr = tid >> 2, vk = (tid & 3) * 4;

    if (vec) {
        #pragma unroll
        for (int l = 0; l < 2; l++) {
            ra4[l] = *(const float4*)&A [(size_t)(row0 + vr + l*64)*lda + vk];
            rb4[l] = *(const float4*)&Bm[(size_t)(col0 + vr + l*64)*ldb + vk];
        }
        #pragma unroll
        for (int l = 0; l < 2; l++) {
            int r = vr + l*64;
            As[0][vk+0][r] = ra4[l].x; As[0][vk+1][r] = ra4[l].y;
            As[0][vk+2][r] = ra4[l].z; As[0][vk+3][r] = ra4[l].w;
            Bs[0][vk+0][r] = rb4[l].x; Bs[0][vk+1][r] = rb4[l].y;
            Bs[0][vk+2][r] = rb4[l].z; Bs[0][vk+3][r] = rb4[l].w;
        }
    } else {
        #pragma unroll
        for (int l = 0; l < 8; l++) {
            int e = tid + l*256;
            int kk = e & 15, r = e >> 4;
            ra[l] = (kk < K) ? A [(size_t)(row0 + r)*lda + kk] : 0.f;
            rb[l] = (kk < K) ? Bm[(size_t)(col0 + r)*ldb + kk] : 0.f;
        }
        #pragma unroll
        for (int l = 0; l < 8; l++) {
            int e = tid + l*256;
            int kk = e & 15, r = e >> 4;
            As[0][kk][r] = ra[l];
            Bs[0][kk][r] = rb[l];
        }
    }
    __syncthreads();

    for (int t = 0; t < nt; t++) {
        int buf = t & 1;
        if (t + 1 < nt) {
            int k0 = (t + 1) * 16;
            if (vec) {
                #pragma unroll
                for (int l = 0; l < 2; l++) {
                    ra4[l] = *(const float4*)&A [(size_t)(row0 + vr + l*64)*lda + k0 + vk];
                    rb4[l] = *(const float4*)&Bm[(size_t)(col0 + vr + l*64)*ldb + k0 + vk];
                }
            } else {
                #pragma unroll
                for (int l = 0; l < 8; l++) {
                    int e = tid + l*256;
                    int kk = e & 15, r = e >> 4;
                    int gk = k0 + kk;
                    ra[l] = (gk < K) ? A [(size_t)(row0 + r)*lda + gk] : 0.f;
                    rb[l] = (gk < K) ? Bm[(size_t)(col0 + r)*ldb + gk] : 0.f;
                }
            }
        }
        #pragma unroll
        for (int kk = 0; kk < 16; kk++) {
            float4 a0 = *(const float4*)&As[buf][kk][ty*4];
            float4 a1 = *(const float4*)&As[buf][kk][ty*4 + 64];
            ulonglong2 bq0 = *(const ulonglong2*)&Bs[buf][kk][tx*4];
            ulonglong2 bq1 = *(const ulonglong2*)&Bs[buf][kk][tx*4 + 64];
            unsigned long long bb[4] = {bq0.x, bq0.y, bq1.x, bq1.y};
            float av[8] = {a0.x, a0.y, a0.z, a0.w, a1.x, a1.y, a1.z, a1.w};
            if (selfbias) {
                #pragma unroll
                for (int j = 0; j < 4; j++) ffma2(sq[j], bb[j], bb[j]);
            }
            #pragma unroll
            for (int i = 0; i < 8; i++) {
                unsigned long long ad = pack2(av[i], av[i]);
                #pragma unroll
                for (int j = 0; j < 4; j++) ffma2(acc[i][j], ad, bb[j]);
            }
        }
        if (t + 1 < nt) {
            int nb = (t + 1) & 1;
            if (vec) {
                #pragma unroll
                for (int l = 0; l < 2; l++) {
                    int r = vr + l*64;
                    As[nb][vk+0][r] = ra4[l].x; As[nb][vk+1][r] = ra4[l].y;
                    As[nb][vk+2][r] = ra4[l].z; As[nb][vk+3][r] = ra4[l].w;
                    Bs[nb][vk+0][r] = rb4[l].x; Bs[nb][vk+1][r] = rb4[l].y;
                    Bs[nb][vk+2][r] = rb4[l].z; Bs[nb][vk+3][r] = rb4[l].w;
                }
            } else {
                #pragma unroll
                for (int l = 0; l < 8; l++) {
                    int e = tid + l*256;
                    int kk = e & 15, r = e >> 4;
                    As[nb][kk][r] = ra[l];
                    Bs[nb][kk][r] = rb[l];
                }
            }
            __syncthreads();
        }
    }
    float bv[8] = {0,0,0,0,0,0,0,0};
    if (selfbias) {
        unpack2(sq[0], bv[0], bv[1]);
        unpack2(sq[1], bv[2], bv[3]);
        unpack2(sq[2], bv[4], bv[5]);
        unpack2(sq[3], bv[6], bv[7]);
        #pragma unroll
        for (int j = 0; j < 8; j++) bv[j] *= -0.5f;
    }
    #pragma unroll
    for (int i = 0; i < 8; i++) {
        int r = row0 + ((i >> 2) << 6) + ty*4 + (i & 3);
        int c0 = col0 + tx*4;
        int c1 = col0 + 64 + tx*4;
        float4 o0, o1;
        unpack2(acc[i][0], o0.x, o0.y);
        unpack2(acc[i][1], o0.z, o0.w);
        unpack2(acc[i][2], o1.x, o1.y);
        unpack2(acc[i][3], o1.z, o1.w);
        o0.x += bv[0]; o0.y += bv[1]; o0.z += bv[2]; o0.w += bv[3];
        o1.x += bv[4]; o1.y += bv[5]; o1.z += bv[6]; o1.w += bv[7];
        if (accum) {
            float4 p0 = *(float4*)&C[(size_t)r*ldc + c0];
            float4 p1 = *(float4*)&C[(size_t)r*ldc + c1];
            o0.x += p0.x; o0.y += p0.y; o0.z += p0.z; o0.w += p0.w;
            o1.x += p1.x; o1.y += p1.y; o1.z += p1.z; o1.w += p1.w;
        }
        *(float4*)&C[(size_t)r*ldc + c0] = o0;
        *(float4*)&C[(size_t)r*ldc + c1] = o1;
    }
}

// -------- warp top-20: multi-admission, incremental heads, NO clearing ------
// Consumed heads are > current h, so the strict (v[j] < h) second-scan
// excludes them automatically; v[] stays read-only after load.
__device__ __forceinline__ void warp_topk20(float (&v)[32], int r, int lane,
                                            int* __restrict__ out) {
    // one-time head tournament (value + slot, ties -> lower slot)
    float h; int hs;
    {
        float tv16[16]; int tj16[16];
        #pragma unroll
        for (int j = 0; j < 16; j++) {
            bool t = v[2*j+1] > v[2*j];
            tv16[j] = t ? v[2*j+1] : v[2*j];
            tj16[j] = t ? 2*j+1 : 2*j;
        }
        float tv8[8]; int tj8[8];
        #pragma unroll
        for (int j = 0; j < 8; j++) {
            bool t = tv16[2*j+1] > tv16[2*j];
            tv8[j] = t ? tv16[2*j+1] : tv16[2*j];
            tj8[j] = t ? tj16[2*j+1] : tj16[2*j];
        }
        float tv4[4]; int tj4[4];
        #pragma unroll
        for (int j = 0; j < 4; j++) {
            bool t = tv8[2*j+1] > tv8[2*j];
            tv4[j] = t ? tv8[2*j+1] : tv8[2*j];
            tj4[j] = t ? tj8[2*j+1] : tj8[2*j];
        }
        float tv2[2]; int tj2[2];
        #pragma unroll
        for (int j = 0; j < 2; j++) {
            bool t = tv4[2*j+1] > tv4[2*j];
            tv2[j] = t ? tv4[2*j+1] : tv4[2*j];
            tj2[j] = t ? tj4[2*j+1] : tj4[2*j];
        }
        bool t0 = tv2[1] > tv2[0];
        h  = t0 ? tv2[1] : tv2[0];
        hs = t0 ? tj2[1] : tj2[0];
    }

    int done = 0;
    while (done < KNN) {
        // per-lane second (value + slot), strictly below head
        float s = -INFINITY; int ss = 0;
        #pragma unroll
        for (int j = 0; j < 32; j++) {
            float t = (v[j] < h) ? v[j] : -INFINITY;
            bool gt = t > s;
            s  = gt ? t : s;
            ss = gt ? j : ss;
        }

        // bitonic sort (head, srclane) ascending across warp
        float hh = h;
        int   sl = lane;
        #pragma unroll
        for (int k = 2; k <= 32; k <<= 1) {
            #pragma unroll
            for (int j = k >> 1; j > 0; j >>= 1) {
                float oh = __shfl_xor_sync(FULLM, hh, j);
                int   ol = __shfl_xor_sync(FULLM, sl, j);
                bool up = ((lane & k) == 0);
                bool oless = (oh < hh) || (oh == hh && ol < sl);
                bool takeMin = (((lane & j) == 0) == up);
                bool pick_o = (oless == takeMin);
                hh = pick_o ? oh : hh;
                sl = pick_o ? ol : sl;
            }
        }
        int di = 31 - lane;

        // seconds routed to sorted order; exclusive prefix-max over higher ranks
        float ssrt = __shfl_sync(FULLM, s, sl);
        float t1 = __shfl_down_sync(FULLM, ssrt, 1);
        float pm = (lane == 31) ? -INFINITY : t1;
        #pragma unroll
        for (int off = 1; off < 32; off <<= 1) {
            float t = __shfl_down_sync(FULLM, pm, off);
            pm = fmaxf(pm, t);
        }

        int need = KNN - done;
        bool iadm = (hh > pm) && (di < need);
        unsigned admmask = __ballot_sync(FULLM, iadm);
        int cnt = __popc(admmask);

        int hsl = __shfl_sync(FULLM, hs, sl);
        int g   = hsl * 32 + sl;
        if (iadm) out[(size_t)r*KNN + done + di] = g;

        // broadcast which source lanes got consumed; promote their heads
        unsigned m = iadm ? (1u << sl) : 0u;
        #pragma unroll
        for (int off = 16; off; off >>= 1)
            m |= __shfl_xor_sync(FULLM, m, off);
        bool promote = (m >> lane) & 1u;
        h  = promote ? s  : h;
        hs = promote ? ss : hs;

        done += cnt;
    }
}

__global__ void __launch_bounds__(256)
topk_warp(const float* __restrict__ S, int* __restrict__ out) {
    int warp = threadIdx.x >> 5, lane = threadIdx.x & 31;
    int r = blockIdx.x * 8 + warp;
    const float* row = S + (size_t)r * NN;
    float v[32];
    #pragma unroll
    for (int j = 0; j < 32; j++) v[j] = row[j*32 + lane];
    warp_topk20(v, r, lane, out);
}

// stage 1 fused: reads x in native (B,3,N) layout
__global__ void __launch_bounds__(256)
score1_topk(const float* __restrict__ x, int* __restrict__ out) {
    int warp = threadIdx.x >> 5, lane = threadIdx.x & 31;
    int r = blockIdx.x * 8 + warp;
    int b = r >> 10, n = r & 1023;
    const float* xb = x + (size_t)b*3*NN;
    float cx = xb[n], cy = xb[NN + n], cz = xb[2*NN + n];
    float v[32];
    #pragma unroll
    for (int j = 0; j < 32; j++) {
        int col = j*32 + lane;
        float xj = xb[col], yj = xb[NN + col], zj = xb[2*NN + col];
        float half = -0.5f * (xj*xj + yj*yj + zj*zj);
        v[j] = fmaf(cx, xj, fmaf(cy, yj, fmaf(cz, zj, half)));
    }
    warp_topk20(v, r, lane, out);
}

// -------- single gather pass: BN stats + per-(point,channel) max --------
__global__ void __launch_bounds__(256)
stats_mm_edge(const float* __restrict__ P, int ldp,
              const float* __restrict__ Q, int ldq,
              const int* __restrict__ idx, int O, int oshift,
              float* __restrict__ part,
              float* __restrict__ Mx) {
    __shared__ int sIdx[16*KNN];
    __shared__ float red1[256], red2[256];
    int b = blockIdx.y, i0 = blockIdx.x * 16;
    for (int e = threadIdx.x; e < 16*KNN; e += 256)
        sIdx[e] = idx[(size_t)(b*NN + i0)*KNN + e];
    __syncthreads();
    int o  = threadIdx.x & (O-1);
    int pp = threadIdx.x >> oshift;
    int PP = 256 >> oshift;
    float s1 = 0.f, s2 = 0.f;
    for (int ii = pp; ii < 16; ii += PP) {
        int gi = b*NN + i0 + ii;
        float qv = Q[(size_t)gi*ldq + o];
        float mx = -1e30f;
        float pv[KNN];
        #pragma unroll
        for (int k = 0; k < KNN; k++) {
            int j = sIdx[ii*KNN + k];
            pv[k] = P[(size_t)(b*NN + j)*ldp + o];
        }
        #pragma unroll
        for (int k = 0; k < KNN; k++) {
            float v = pv[k] + qv;
            s1 += v; s2 += v*v;
            mx = fmaxf(mx, v);
        }
        Mx[(size_t)gi*O + o] = mx;
    }
    red1[threadIdx.x] = s1; red2[threadIdx.x] = s2;
    __syncthreads();
    if (pp == 0) {
        for (int p = 1; p < PP; p++) { s1 += red1[o + p*O]; s2 += red2[o + p*O]; }
        int grp = blockIdx.y * 64 + blockIdx.x;   // < 512
        part[(size_t)grp*O + o]         = s1;
        part[(size_t)(512 + grp)*O + o] = s2;
    }
}

// grid (64, BB), 512 threads, 16 points/block
__global__ void stats_plain(const float* __restrict__ P, float* __restrict__ part) {
    int b = blockIdx.y, i0 = blockIdx.x * 16;
    int o = threadIdx.x;  // 512
    float s1 = 0.f, s2 = 0.f;
    #pragma unroll
    for (int ii = 0; ii < 16; ii++) {
        float v = P[(size_t)(b*NN + i0 + ii)*512 + o];
        s1 += v; s2 += v*v;
    }
    int grp = blockIdx.y * 64 + blockIdx.x;
    part[(size_t)grp*512 + o]         = s1;
    part[(size_t)(512 + grp)*512 + o] = s2;
}

// warp-per-channel reduction over 512 groups. grid = O/8, block = 256.
__global__ void __launch_bounds__(256)
reduce_stats(int O, float cnt, const float* __restrict__ part,
             float* __restrict__ mean, float* __restrict__ istd) {
    int warp = threadIdx.x >> 5, lane = threadIdx.x & 31;
    int o = blockIdx.x*8 + warp;
    float s1 = 0.f, s2 = 0.f;
    #pragma unroll
    for (int g = lane; g < 512; g += 32) {
        s1 += part[(size_t)g*O + o];
        s2 += part[(size_t)(512 + g)*O + o];
    }
    #pragma unroll
    for (int off = 16; off; off >>= 1) {
        s1 += __shfl_down_sync(FULLM, s1, off);
        s2 += __shfl_down_sync(FULLM, s2, off);
    }
    if (lane == 0) {
        float m = s1 / cnt;
        float var = s2 / cnt - m*m;
        mean[o] = m;
        istd[o] = rsqrtf(var + EPS);
    }
}

// -------- vectorized finalize from max (monotone BN+lrelu, scale>=0) --------
__global__ void __launch_bounds__(256)
finalize_mm4(const float4* __restrict__ Mx,
             int O, int oshift, int choff,
             const float4* __restrict__ ga, const float4* __restrict__ be,
             const float4* __restrict__ mean, const float4* __restrict__ istd,
             float* __restrict__ XCAT) {
    int t4 = blockIdx.x*256 + threadIdx.x;
    int gi = t4 >> (oshift - 2);
    int oq = t4 & ((O >> 2) - 1);
    float4 m = mean[oq], is = istd[oq], g = ga[oq], b = be[oq];
    float4 mx = Mx[t4];
    float4 r;
    {
        float sc = is.x * g.x;
        float z = (mx.x - m.x)*sc + b.x; r.x = (z >= 0.f) ? z : NEG*z;
    }
    {
        float sc = is.y * g.y;
        float z = (mx.y - m.y)*sc + b.y; r.y = (z >= 0.f) ? z : NEG*z;
    }
    {
        float sc = is.z * g.z;
        float z = (mx.z - m.z)*sc + b.z; r.z = (z >= 0.f) ? z : NEG*z;
    }
    {
        float sc = is.w * g.w;
        float z = (mx.w - m.w)*sc + b.w; r.w = (z >= 0.f) ? z : NEG*z;
    }
    *(float4*)&XCAT[(size_t)gi*512 + choff + oq*4] = r;
}

// -------- final BN+lrelu with transposed write to d_out (B,512,N) --------
__global__ void finalize5(const float* __restrict__ P,
                          const float* __restrict__ ga, const float* __restrict__ be,
                          const float* __restrict__ mean, const float* __restrict__ istd,
                          float* __restrict__ out) {
    __shared__ float tile[32][33];
    int b = blockIdx.z, o0 = blockIdx.y * 32, n0 = blockIdx.x * 32;
    int tid = threadIdx.x;
    #pragma unroll
    for (int l = 0; l < 4; l++) {
        int e = tid + l*256;
        int nn = e >> 5, oo = e & 31;
        int o = o0 + oo;
        float v = P[(size_t)(b*NN + n0 + nn)*512 + o];
        v = (v - mean[o]) * istd[o] * ga[o] + be[o];
        v = (v >= 0.f) ? v : NEG*v;
        tile[oo][nn] = v;
    }
    __syncthreads();
    #pragma unroll
    for (int l = 0; l < 4; l++) {
        int e = tid + l*256;
        int oo = e >> 5, nn = e & 31;
        out[(size_t)b*512*NN + (size_t)(o0 + oo)*NN + n0 + nn] = tile[oo][nn];
    }
}

extern "C" void kernel_launch(void* const* d_in, const int* in_sizes, int n_in,
                              void* d_out, int out_size) {
    const float* x  = (const float*)d_in[0];
    const float* y  = (const float*)d_in[1];
    const float* w1 = (const float*)d_in[2];
    const float* w2 = (const float*)d_in[3];
    const float* w3 = (const float*)d_in[4];
    const float* w4 = (const float*)d_in[5];
    const float* w5 = (const float*)d_in[6];
    const float* g1 = (const float*)d_in[7];  const float* b1 = (const float*)d_in[8];
    const float* g2 = (const float*)d_in[9];  const float* b2 = (const float*)d_in[10];
    const float* g3 = (const float*)d_in[11]; const float* b3 = (const float*)d_in[12];
    const float* g4 = (const float*)d_in[13]; const float* b4 = (const float*)d_in[14];
    const float* g5 = (const float*)d_in[15]; const float* b5 = (const float*)d_in[16];
    float* out = (float*)d_out;

    float *yT, *ynT, *XCAT, *S, *P, *P5, *Q, *Wc, *part, *mean, *istd;
    int* idx;
    cudaGetSymbolAddress((void**)&yT,  g_yT);
    cudaGetSymbolAddress((void**)&ynT, g_ynT);
    cudaGetSymbolAddress((void**)&XCAT,g_XCAT);
    cudaGetSymbolAddress((void**)&S,   g_S);
    cudaGetSymbolAddress((void**)&P,   g_P);
    cudaGetSymbolAddress((void**)&P5,  g_P5);
    cudaGetSymbolAddress((void**)&Q,   g_Q);
    cudaGetSymbolAddress((void**)&Wc,  g_Wc);
    cudaGetSymbolAddress((void**)&idx, g_idx);
    cudaGetSymbolAddress((void**)&part,g_part);
    cudaGetSymbolAddress((void**)&mean,g_mean);
    cudaGetSymbolAddress((void**)&istd,g_istd);

    float* Mx = S;                 // S is free outside score/topk windows
    const size_t SH  = (size_t)HB*NN*NN;     // S offset for half B
    const size_t RH  = (size_t)HB*NN;        // row offset for half B

    cudaStream_t s1;
    cudaStreamCreateWithFlags(&s1, cudaStreamNonBlocking);
    cudaEvent_t evF, evP1, evP2, evP3, evQ4, evP5a, evF1, evF2, evF3;
    cudaEvent_t evA2, evB2, evA3, evB3, evA4, evB4;
    cudaEvent_t* evs[] = {&evF,&evP1,&evP2,&evP3,&evQ4,&evP5a,&evF1,&evF2,&evF3,
                          &evA2,&evB2,&evA3,&evB3,&evA4,&evB4};
    for (auto e : evs) cudaEventCreateWithFlags(e, cudaEventDisableTiming);

    // fork
    cudaEventRecord(evF, 0);
    cudaStreamWaitEvent(s1, evF, 0);

    // side: y prep + weights + stage-1 P + EARLY stage-4 gathered operand
    prep_y<<<BN, 128, 0, s1>>>(y, yT, ynT);
    make_weights<<<226, 256, 0, s1>>>(w1, w2, w3, w4, Wc);
    pq1_kernel<<<BN*32/256, 256, 0, s1>>>(x, Wc, P);
    cudaEventRecord(evP1, s1);
    gemm128<<<dim3(2,64,1), 256, 0, s1>>>(128, 1, 0, 0, yT, 128, 0, w4, 256, 0, Q, 256, 0);

    // main: stage 1
    score1_topk<<<BN/8, 256>>>(x, idx);
    cudaStreamWaitEvent(0, evP1, 0);
    stats_mm_edge<<<dim3(64,8), 256>>>(P, 128, P+64, 128, idx, 64, 6, part, Mx);
    reduce_stats<<<8, 256>>>(64, 163840.f, part, mean, istd);
    finalize_mm4<<<BN*64/1024, 256>>>((float4*)Mx, 64, 6, 0,
        (const float4*)g1, (const float4*)b1, (const float4*)mean, (const float4*)istd, XCAT);
    cudaEventRecord(evF1, 0);

    // side: stage2 PQ gemm
    cudaStreamWaitEvent(s1, evF1, 0);
    gemm128<<<dim3(1,64,1), 256, 0, s1>>>(64, 1, 0, 0, XCAT, 512, 0, Wc+WS2, 64, 0, P, 128, 0);
    cudaEventRecord(evP2, s1);

    // main: stage 2 (pipelined score halves)
    gemm128<<<dim3(8,8,HB), 256>>>(64, 1, 1, 0, XCAT, 512, NN*512, XCAT, 512, NN*512, S, NN, NN*NN);
    cudaEventRecord(evA2, 0);
    cudaStreamWaitEvent(s1, evA2, 0);
    gemm128<<<dim3(8,8,HB), 256, 0, s1>>>(64, 1, 1, 0, XCAT + RH*512, 512, NN*512,
                                          XCAT + RH*512, 512, NN*512, S + SH, NN, NN*NN);
    cudaEventRecord(evB2, s1);
    topk_warp<<<RH/8, 256>>>(S, idx);
    cudaStreamWaitEvent(0, evB2, 0);
    topk_warp<<<RH/8, 256>>>(S + SH, idx + RH*KNN);
    cudaStreamWaitEvent(0, evP2, 0);
    stats_mm_edge<<<dim3(64,8), 256>>>(P, 128, P+64, 128, idx, 64, 6, part, Mx);
    reduce_stats<<<8, 256>>>(64, 163840.f, part, mean, istd);
    finalize_mm4<<<BN*64/1024, 256>>>((float4*)Mx, 64, 6, 64,
        (const float4*)g2, (const float4*)b2, (const float4*)mean, (const float4*)istd, XCAT);
    cudaEventRecord(evF2, 0);

    // side: stage3 PQ gemm
    cudaStreamWaitEvent(s1, evF2, 0);
    gemm128<<<dim3(2,64,1), 256, 0, s1>>>(64, 1, 0, 0, XCAT + 64, 512, 0, Wc+WS3, 64, 0, P, 256, 0);
    cudaEventRecord(evP3, s1);

    // main: stage 3 (pipelined score halves)
    gemm128<<<dim3(8,8,HB), 256>>>(64, 1, 1, 0, XCAT + 64, 512, NN*512, XCAT + 64, 512, NN*512, S, NN, NN*NN);
    cudaEventRecord(evA3, 0);
    cudaStreamWaitEvent(s1, evA3, 0);
    gemm128<<<dim3(8,8,HB), 256, 0, s1>>>(64, 1, 1, 0, XCAT + 64 + RH*512, 512, NN*512,
                                          XCAT + 64 + RH*512, 512, NN*512, S + SH, NN, NN*NN);
    cudaEventRecord(evB3, s1);
    topk_warp<<<RH/8, 256>>>(S, idx);
    cudaStreamWaitEvent(0, evB3, 0);
    topk_warp<<<RH/8, 256>>>(S + SH, idx + RH*KNN);
    cudaStreamWaitEvent(0, evP3, 0);
    stats_mm_edge<<<dim3(64,8), 256>>>(P, 256, P+128, 256, idx, 128, 7, part, Mx);
    reduce_stats<<<16, 256>>>(128, 163840.f, part, mean, istd);
    finalize_mm4<<<BN*128/1024, 256>>>((float4*)Mx, 128, 7, 128,
        (const float4*)g3, (const float4*)b3, (const float4*)mean, (const float4*)istd, XCAT);
    cudaEventRecord(evF3, 0);

    // main: stage 4 (pipelined score halves)
    gemm128<<<dim3(8,8,HB), 256>>>(128, 1, 0, 0, XCAT + 128, 512, NN*512, ynT, 128, NN*128,
                                   S, NN, NN*NN);
    cudaEventRecord(evA4, 0);
    // side: second score half first (so topkB isn't delayed), then Wc4, P5a
    cudaStreamWaitEvent(s1, evA4, 0);
    gemm128<<<dim3(8,8,HB), 256, 0, s1>>>(128, 1, 0, 0, XCAT + 128 + RH*512, 512, NN*512,
                                          ynT + RH*128, 128, NN*128, S + SH, NN, NN*NN);
    cudaEventRecord(evB4, s1);
    gemm128<<<dim3(2,64,1), 256, 0, s1>>>(128, 1, 0, 0, XCAT + 128, 512, 0, Wc+WS4, 128, 0, P, 256, 0);
    cudaEventRecord(evQ4, s1);
    gemm128<<<dim3(4,64,1), 256, 0, s1>>>(256, 1, 0, 0, XCAT, 512, 0, w5, 512, 0, P5, 512, 0);
    cudaEventRecord(evP5a, s1);

    topk_warp<<<RH/8, 256>>>(S, idx);
    cudaStreamWaitEvent(0, evB4, 0);
    topk_warp<<<RH/8, 256>>>(S + SH, idx + RH*KNN);
    cudaStreamWaitEvent(0, evQ4, 0);
    stats_mm_edge<<<dim3(64,8), 256>>>(Q, 256, P, 256, idx, 256, 8, part, Mx);
    reduce_stats<<<32, 256>>>(256, 163840.f, part, mean, istd);
    finalize_mm4<<<BN*256/1024, 256>>>((float4*)Mx, 256, 8, 256,
        (const float4*)g4, (const float4*)b4, (const float4*)mean, (const float4*)istd, XCAT);

    // main: stage 5 (second K-half accumulates onto side-computed first half)
    cudaStreamWaitEvent(0, evP5a, 0);
    gemm128<<<dim3(4,64,1), 256>>>(256, 1, 0, 1, XCAT + 256, 512, 0, w5 + 256, 512, 0, P5, 512, 0);
    stats_plain<<<dim3(64,8), 512>>>(P5, part);
    reduce_stats<<<64, 256>>>(512, 8192.f, part, mean, istd);
    finalize5<<<dim3(32,16,8), 256>>>(P5, g5, b5, mean, istd, out);
}

// round 14
// speedup vs baseline: 1.0725x; 1.0725x over previous
#include <cuda_runtime.h>
#include <math.h>

#define BB 8
#define NN 1024
#define BN (BB*NN)
#define KNN 20
#define NEG 0.2f
#define EPS 1e-5f
#define FULLM 0xffffffffu

// weight regions inside g_Wc
#define WS1 0        // stacked w1: 128 x 3   (384)
#define WS2 512      // stacked w2: 128 x 64  (8192)
#define WS3 9216     // stacked w3: 256 x 64  (16384)
#define WS4 26112    // diff   w4: 256 x 128  (32768)  end=58880

// -------- scratch (device globals; no allocation allowed) --------
__device__ float g_yT[BN*128];        // y transposed (B,M,128)
__device__ float g_ynT[BN*128];       // y normalized transposed
__device__ float g_XCAT[BN*512];      // concat of x1|x2|x3|x4 per point
__device__ float g_S[BB*NN*NN];       // score matrices (32MB); reused as Mx
__device__ float g_P[BN*512];         // PQ scratch
__device__ float g_P5[BN*512];        // stage5 pre-BN output (split-K accumulator)
__device__ float g_Q[BN*256];         // stage4 gathered operand (yT @ w4)
__device__ float g_Wc[64*1024];       // all prepped weights
__device__ int   g_idx[BN*KNN];       // knn indices
__device__ float g_part[2*512*512];   // BN partial sums
__device__ float g_mean[512];
__device__ float g_istd[512];

// -------- f32x2 packed helpers --------
__device__ __forceinline__ unsigned long long pack2(float x, float y) {
    unsigned long long r;
    asm("mov.b64 %0, {%1, %2};" : "=l"(r) : "f"(x), "f"(y));
    return r;
}
__device__ __forceinline__ void unpack2(unsigned long long v, float& x, float& y) {
    asm("mov.b64 {%0, %1}, %2;" : "=f"(x), "=f"(y) : "l"(v));
}
__device__ __forceinline__ void ffma2(unsigned long long& d,
                                      unsigned long long a, unsigned long long b) {
    asm("fma.rn.f32x2 %0, %1, %2, %0;" : "+l"(d) : "l"(a), "l"(b));
}

// -------- small prep kernels --------
__global__ void prep_y(const float* __restrict__ y, float* __restrict__ yT,
                       float* __restrict__ ynT) {
    int m = blockIdx.x;            // global point 0..8191
    int b = m >> 10, mm = m & 1023;
    int c = threadIdx.x;           // 128
    float v = y[((size_t)b*128 + c)*NN + mm];
    __shared__ float red[128];
    red[c] = v*v;
    __syncthreads();
    for (int s = 64; s > 0; s >>= 1) {
        if (c < s) red[c] += red[c+s];
        __syncthreads();
    }
    float nrm = sqrtf(red[0]);
    float sc = 1.0f / fmaxf(nrm, 1e-12f);
    yT [(size_t)m*128 + c] = v;
    ynT[(size_t)m*128 + c] = v * sc;
}

// one kernel prepping all weights
__global__ void make_weights(const float* __restrict__ w1, const float* __restrict__ w2,
                             const float* __restrict__ w3, const float* __restrict__ w4,
                             float* __restrict__ out) {
    int e = blockIdx.x*blockDim.x + threadIdx.x;
    if (e < 384) {
        int r = e / 3, c = e % 3;
        float v = (r < 64) ? w1[r*6 + c]
                           : w1[(r-64)*6 + 3 + c] - w1[(r-64)*6 + c];
        out[WS1 + e] = v;
    }
    int e2 = e - 384;
    if (e2 >= 0 && e2 < 8192) {
        int r = e2 >> 6, c = e2 & 63;
        float v = (r < 64) ? w2[r*128 + c]
                           : w2[(r-64)*128 + 64 + c] - w2[(r-64)*128 + c];
        out[WS2 + e2] = v;
    }
    int e3 = e2 - 8192;
    if (e3 >= 0 && e3 < 16384) {
        int r = e3 >> 6, c = e3 & 63;
        float v = (r < 128) ? w3[r*128 + c]
                            : w3[(r-128)*128 + 64 + c] - w3[(r-128)*128 + c];
        out[WS3 + e3] = v;
    }
    int e4 = e3 - 16384;
    if (e4 >= 0 && e4 < 32768) {
        int r = e4 >> 7, c = e4 & 127;
        out[WS4 + e4] = w4[r*256 + 128 + c] - w4[r*256 + c];
    }
}

// -------- stage-1 PQ: P[r][c] = sum_{k<3} x[b,k,n] * Wc1[c][k] -------------
__global__ void __launch_bounds__(256)
pq1_kernel(const float* __restrict__ x, const float* __restrict__ Wc,
           float* __restrict__ P) {
    __shared__ float w[384];
    for (int e = threadIdx.x; e < 384; e += 256) w[e] = Wc[WS1 + e];
    __syncthreads();
    int t = blockIdx.x*256 + threadIdx.x;
    int r = t >> 5;
    int cq = (t & 31) * 4;
    int b = r >> 10, n = r & 1023;
    float a0 = x[((size_t)b*3 + 0)*NN + n];
    float a1 = x[((size_t)b*3 + 1)*NN + n];
    float a2 = x[((size_t)b*3 + 2)*NN + n];
    float4 o;
    o.x = fmaf(a2, w[(cq+0)*3+2], fmaf(a1, w[(cq+0)*3+1], fmaf(a0, w[(cq+0)*3+0], 0.f)));
    o.y = fmaf(a2, w[(cq+1)*3+2], fmaf(a1, w[(cq+1)*3+1], fmaf(a0, w[(cq+1)*3+0], 0.f)));
    o.z = fmaf(a2, w[(cq+2)*3+2], fmaf(a1, w[(cq+2)*3+1], fmaf(a0, w[(cq+2)*3+0], 0.f)));
    o.w = fmaf(a2, w[(cq+3)*3+2], fmaf(a1, w[(cq+3)*3+1], fmaf(a0, w[(cq+3)*3+0], 0.f)));
    *(float4*)&P[(size_t)r*128 + cq] = o;
}

// -------- GEMM: C[r][c] (+)= sum_k A[r][k]*B[c][k] (+ selfbias) --------------
__global__ void __launch_bounds__(256, 2)
gemm128(int K, int vec, int selfbias, int accum,
        const float* __restrict__ A, int lda, int sA,
        const float* __restrict__ Bm, int ldb, int sB,
        float* __restrict__ C, int ldc, int sC) {
    __shared__ __align__(16) float As[2][16][132];
    __shared__ __align__(16) float Bs[2][16][132];
    int z = blockIdx.z;
    A  += (size_t)z * sA;
    Bm += (size_t)z * sB;
    C  += (size_t)z * sC;
    int row0 = blockIdx.y * 128, col0 = blockIdx.x * 128;
    int tid = threadIdx.x;
    int ty = tid >> 4, tx = tid & 15;

    unsigned long long acc[8][4];
    #pragma unroll
    for (int i = 0; i < 8; i++)
        #pragma unroll
        for (int j = 0; j < 4; j++) acc[i][j] = 0ULL;
    unsigned long long sq[4] = {0ULL, 0ULL, 0ULL, 0ULL};

    int nt = (K + 15) / 16;
    float ra[8], rb[8];
    float4 ra4[2], rb4[2];
    int vr = tid >> 2, vk = (tid & 3) * 4;

    if (vec) {
        #pragma unroll
        for (int l = 0; l < 2; l++) {
            ra4[l] = *(const float4*)&A [(size_t)(row0 + vr + l*64)*lda + vk];
            rb4[l] = *(const float4*)&Bm[(size_t)(col0 + vr + l*64)*ldb + vk];
        }
        #pragma unroll
        for (int l = 0; l < 2; l++) {
            int r = vr + l*64;
            As[0][vk+0][r] = ra4[l].x; As[0][vk+1][r] = ra4[l].y;
            As[0][vk+2][r] = ra4[l].z; As[0][vk+3][r] = ra4[l].w;
            Bs[0][vk+0][r] = rb4[l].x; Bs[0][vk+1][r] = rb4[l].y;
            Bs[0][vk+2][r] = rb4[l].z; Bs[0][vk+3][r] = rb4[l].w;
        }
    } else {
        #pragma unroll
        for (int l = 0; l < 8; l++) {
            int e = tid + l*256;
            int kk = e & 15, r = e >> 4;
            ra[l] = (kk < K) ? A [(size_t)(row0 + r)*lda + kk] : 0.f;
            rb[l] = (kk < K) ? Bm[(size_t)(col0 + r)*ldb + kk] : 0.f;
        }
        #pragma unroll
        for (int l = 0; l < 8; l++) {
            int e = tid + l*256;
            int kk = e & 15, r = e >> 4;
            As[0][kk][r] = ra[l];
            Bs[0][kk][r] = rb[l];
        }
    }
    __syncthreads();

    for (int t = 0; t < nt; t++) {
        int buf = t & 1;
        if (t + 1 < nt) {
            int k0 = (t + 1) * 16;
            if (vec) {
                #pragma unroll
                for (int l = 0; l < 2; l++) {
                    ra4[l] = *(const float4*)&A [(size_t)(row0 + vr + l*64)*lda + k0 + vk];
                    rb4[l] = *(const float4*)&Bm[(size_t)(col0 + vr + l*64)*ldb + k0 + vk];
                }
            } else {
                #pragma unroll
                for (int l = 0; l < 8; l++) {
                    int e = tid + l*256;
                    int kk = e & 15, r = e >> 4;
                    int gk = k0 + kk;
                    ra[l] = (gk < K) ? A [(size_t)(row0 + r)*lda + gk] : 0.f;
                    rb[l] = (gk < K) ? Bm[(size_t)(col0 + r)*ldb + gk] : 0.f;
                }
            }
        }
        #pragma unroll
        for (int kk = 0; kk < 16; kk++) {
            float4 a0 = *(const float4*)&As[buf][kk][ty*4];
            float4 a1 = *(const float4*)&As[buf][kk][ty*4 + 64];
            ulonglong2 bq0 = *(const ulonglong2*)&Bs[buf][kk][tx*4];
            ulonglong2 bq1 = *(const ulonglong2*)&Bs[buf][kk][tx*4 + 64];
            unsigned long long bb[4] = {bq0.x, bq0.y, bq1.x, bq1.y};
            float av[8] = {a0.x, a0.y, a0.z, a0.w, a1.x, a1.y, a1.z, a1.w};
            if (selfbias) {
                #pragma unroll
                for (int j = 0; j < 4; j++) ffma2(sq[j], bb[j], bb[j]);
            }
            #pragma unroll
            for (int i = 0; i < 8; i++) {
                unsigned long long ad = pack2(av[i], av[i]);
                #pragma unroll
                for (int j = 0; j < 4; j++) ffma2(acc[i][j], ad, bb[j]);
            }
        }
        if (t + 1 < nt) {
            int nb = (t + 1) & 1;
            if (vec) {
                #pragma unroll
                for (int l = 0; l < 2; l++) {
                    int r = vr + l*64;
                    As[nb][vk+0][r] = ra4[l].x; As[nb][vk+1][r] = ra4[l].y;
                    As[nb][vk+2][r] = ra4[l].z; As[nb][vk+3][r] = ra4[l].w;
                    Bs[nb][vk+0][r] = rb4[l].x; Bs[nb][vk+1][r] = rb4[l].y;
                    Bs[nb][vk+2][r] = rb4[l].z; Bs[nb][vk+3][r] = rb4[l].w;
                }
            } else {
                #pragma unroll
                for (int l = 0; l < 8; l++) {
                    int e = tid + l*256;
                    int kk = e & 15, r = e >> 4;
                    As[nb][kk][r] = ra[l];
                    Bs[nb][kk][r] = rb[l];
                }
            }
            __syncthreads();
        }
    }
    float bv[8] = {0,0,0,0,0,0,0,0};
    if (selfbias) {
        unpack2(sq[0], bv[0], bv[1]);
        unpack2(sq[1], bv[2], bv[3]);
        unpack2(sq[2], bv[4], bv[5]);
        unpack2(sq[3], bv[6], bv[7]);
        #pragma unroll
        for (int j = 0; j < 8; j++) bv[j] *= -0.5f;
    }
    #pragma unroll
    for (int i = 0; i < 8; i++) {
        int r = row0 + ((i >> 2) << 6) + ty*4 + (i & 3);
        int c0 = col0 + tx*4;
        int c1 = col0 + 64 + tx*4;
        float4 o0, o1;
        unpack2(acc[i][0], o0.x, o0.y);
        unpack2(acc[i][1], o0.z, o0.w);
        unpack2(acc[i][2], o1.x, o1.y);
        unpack2(acc[i][3], o1.z, o1.w);
        o0.x += bv[0]; o0.y += bv[1]; o0.z += bv[2]; o0.w += bv[3];
        o1.x += bv[4]; o1.y += bv[5]; o1.z += bv[6]; o1.w += bv[7];
        if (accum) {
            float4 p0 = *(float4*)&C[(size_t)r*ldc + c0];
            float4 p1 = *(float4*)&C[(size_t)r*ldc + c1];
            o0.x += p0.x; o0.y += p0.y; o0.z += p0.z; o0.w += p0.w;
            o1.x += p1.x; o1.y += p1.y; o1.z += p1.z; o1.w += p1.w;
        }
        *(float4*)&C[(size_t)r*ldc + c0] = o0;
        *(float4*)&C[(size_t)r*ldc + c1] = o1;
    }
}

// -------- warp top-20: multi-admission, incremental heads, NO clearing ------
// Consumed heads are > current h, so the strict (v[j] < h) second-scan
// excludes them automatically; v[] stays read-only after load.
__device__ __forceinline__ void warp_topk20(float (&v)[32], int r, int lane,
                                            int* __restrict__ out) {
    // one-time head tournament (value + slot, ties -> lower slot)
    float h; int hs;
    {
        float tv16[16]; int tj16[16];
        #pragma unroll
        for (int j = 0; j < 16; j++) {
            bool t = v[2*j+1] > v[2*j];
            tv16[j] = t ? v[2*j+1] : v[2*j];
            tj16[j] = t ? 2*j+1 : 2*j;
        }
        float tv8[8]; int tj8[8];
        #pragma unroll
        for (int j = 0; j < 8; j++) {
            bool t = tv16[2*j+1] > tv16[2*j];
            tv8[j] = t ? tv16[2*j+1] : tv16[2*j];
            tj8[j] = t ? tj16[2*j+1] : tj16[2*j];
        }
        float tv4[4]; int tj4[4];
        #pragma unroll
        for (int j = 0; j < 4; j++) {
            bool t = tv8[2*j+1] > tv8[2*j];
            tv4[j] = t ? tv8[2*j+1] : tv8[2*j];
            tj4[j] = t ? tj8[2*j+1] : tj8[2*j];
        }
        float tv2[2]; int tj2[2];
        #pragma unroll
        for (int j = 0; j < 2; j++) {
            bool t = tv4[2*j+1] > tv4[2*j];
            tv2[j] = t ? tv4[2*j+1] : tv4[2*j];
            tj2[j] = t ? tj4[2*j+1] : tj4[2*j];
        }
        bool t0 = tv2[1] > tv2[0];
        h  = t0 ? tv2[1] : tv2[0];
        hs = t0 ? tj2[1] : tj2[0];
    }

    int done = 0;
    while (done < KNN) {
        // per-lane second (value + slot), strictly below head
        float s = -INFINITY; int ss = 0;
        #pragma unroll
        for (int j = 0; j < 32; j++) {
            float t = (v[j] < h) ? v[j] : -INFINITY;
            bool gt = t > s;
            s  = gt ? t : s;
            ss = gt ? j : ss;
        }

        // bitonic sort (head, srclane) ascending across warp
        float hh = h;
        int   sl = lane;
        #pragma unroll
        for (int k = 2; k <= 32; k <<= 1) {
            #pragma unroll
            for (int j = k >> 1; j > 0; j >>= 1) {
                float oh = __shfl_xor_sync(FULLM, hh, j);
                int   ol = __shfl_xor_sync(FULLM, sl, j);
                bool up = ((lane & k) == 0);
                bool oless = (oh < hh) || (oh == hh && ol < sl);
                bool takeMin = (((lane & j) == 0) == up);
                bool pick_o = (oless == takeMin);
                hh = pick_o ? oh : hh;
                sl = pick_o ? ol : sl;
            }
        }
        int di = 31 - lane;

        // seconds routed to sorted order; exclusive prefix-max over higher ranks
        float ssrt = __shfl_sync(FULLM, s, sl);
        float t1 = __shfl_down_sync(FULLM, ssrt, 1);
        float pm = (lane == 31) ? -INFINITY : t1;
        #pragma unroll
        for (int off = 1; off < 32; off <<= 1) {
            float t = __shfl_down_sync(FULLM, pm, off);
            pm = fmaxf(pm, t);
        }

        int need = KNN - done;
        bool iadm = (hh > pm) && (di < need);
        unsigned admmask = __ballot_sync(FULLM, iadm);
        int cnt = __popc(admmask);

        int hsl = __shfl_sync(FULLM, hs, sl);
        int g   = hsl * 32 + sl;
        if (iadm) out[(size_t)r*KNN + done + di] = g;

        // broadcast which source lanes got consumed; promote their heads
        unsigned m = iadm ? (1u << sl) : 0u;
        #pragma unroll
        for (int off = 16; off; off >>= 1)
            m |= __shfl_xor_sync(FULLM, m, off);
        bool promote = (m >> lane) & 1u;
        h  = promote ? s  : h;
        hs = promote ? ss : hs;

        done += cnt;
    }
}

__global__ void __launch_bounds__(256)
topk_warp(const float* __restrict__ S, int* __restrict__ out) {
    int warp = threadIdx.x >> 5, lane = threadIdx.x & 31;
    int r = blockIdx.x * 8 + warp;
    const float* row = S + (size_t)r * NN;
    float v[32];
    #pragma unroll
    for (int j = 0; j < 32; j++) v[j] = row[j*32 + lane];
    warp_topk20(v, r, lane, out);
}

// stage 1 fused: reads x in native (B,3,N) layout
__global__ void __launch_bounds__(256)
score1_topk(const float* __restrict__ x, int* __restrict__ out) {
    int warp = threadIdx.x >> 5, lane = threadIdx.x & 31;
    int r = blockIdx.x * 8 + warp;
    int b = r >> 10, n = r & 1023;
    const float* xb = x + (size_t)b*3*NN;
    float cx = xb[n], cy = xb[NN + n], cz = xb[2*NN + n];
    float v[32];
    #pragma unroll
    for (int j = 0; j < 32; j++) {
        int col = j*32 + lane;
        float xj = xb[col], yj = xb[NN + col], zj = xb[2*NN + col];
        float half = -0.5f * (xj*xj + yj*yj + zj*zj);
        v[j] = fmaf(cx, xj, fmaf(cy, yj, fmaf(cz, zj, half)));
    }
    warp_topk20(v, r, lane, out);
}

// -------- single gather pass: BN stats + per-(point,channel) max --------
__global__ void __launch_bounds__(256)
stats_mm_edge(const float* __restrict__ P, int ldp,
              const float* __restrict__ Q, int ldq,
              const int* __restrict__ idx, int O, int oshift,
              float* __restrict__ part,
              float* __restrict__ Mx) {
    __shared__ int sIdx[16*KNN];
    __shared__ float red1[256], red2[256];
    int b = blockIdx.y, i0 = blockIdx.x * 16;
    for (int e = threadIdx.x; e < 16*KNN; e += 256)
        sIdx[e] = idx[(size_t)(b*NN + i0)*KNN + e];
    __syncthreads();
    int o  = threadIdx.x & (O-1);
    int pp = threadIdx.x >> oshift;
    int PP = 256 >> oshift;
    float s1 = 0.f, s2 = 0.f;
    for (int ii = pp; ii < 16; ii += PP) {
        int gi = b*NN + i0 + ii;
        float qv = Q[(size_t)gi*ldq + o];
        float mx = -1e30f;
        float pv[KNN];
        #pragma unroll
        for (int k = 0; k < KNN; k++) {
            int j = sIdx[ii*KNN + k];
            pv[k] = P[(size_t)(b*NN + j)*ldp + o];
        }
        #pragma unroll
        for (int k = 0; k < KNN; k++) {
            float v = pv[k] + qv;
            s1 += v; s2 += v*v;
            mx = fmaxf(mx, v);
        }
        Mx[(size_t)gi*O + o] = mx;
    }
    red1[threadIdx.x] = s1; red2[threadIdx.x] = s2;
    __syncthreads();
    if (pp == 0) {
        for (int p = 1; p < PP; p++) { s1 += red1[o + p*O]; s2 += red2[o + p*O]; }
        int grp = blockIdx.y * 64 + blockIdx.x;   // < 512
        part[(size_t)grp*O + o]         = s1;
        part[(size_t)(512 + grp)*O + o] = s2;
    }
}

// grid (64, BB), 512 threads, 16 points/block
__global__ void stats_plain(const float* __restrict__ P, float* __restrict__ part) {
    int b = blockIdx.y, i0 = blockIdx.x * 16;
    int o = threadIdx.x;  // 512
    float s1 = 0.f, s2 = 0.f;
    #pragma unroll
    for (int ii = 0; ii < 16; ii++) {
        float v = P[(size_t)(b*NN + i0 + ii)*512 + o];
        s1 += v; s2 += v*v;
    }
    int grp = blockIdx.y * 64 + blockIdx.x;
    part[(size_t)grp*512 + o]         = s1;
    part[(size_t)(512 + grp)*512 + o] = s2;
}

// warp-per-channel reduction over 512 groups. grid = O/8, block = 256.
__global__ void __launch_bounds__(256)
reduce_stats(int O, float cnt, const float* __restrict__ part,
             float* __restrict__ mean, float* __restrict__ istd) {
    int warp = threadIdx.x >> 5, lane = threadIdx.x & 31;
    int o = blockIdx.x*8 + warp;
    float s1 = 0.f, s2 = 0.f;
    #pragma unroll
    for (int g = lane; g < 512; g += 32) {
        s1 += part[(size_t)g*O + o];
        s2 += part[(size_t)(512 + g)*O + o];
    }
    #pragma unroll
    for (int off = 16; off; off >>= 1) {
        s1 += __shfl_down_sync(FULLM, s1, off);
        s2 += __shfl_down_sync(FULLM, s2, off);
    }
    if (lane == 0) {
        float m = s1 / cnt;
        float var = s2 / cnt - m*m;
        mean[o] = m;
        istd[o] = rsqrtf(var + EPS);
    }
}

// -------- vectorized finalize from max (monotone BN+lrelu, scale>=0) --------
__global__ void __launch_bounds__(256)
finalize_mm4(const float4* __restrict__ Mx,
             int O, int oshift, int choff,
             const float4* __restrict__ ga, const float4* __restrict__ be,
             const float4* __restrict__ mean, const float4* __restrict__ istd,
             float* __restrict__ XCAT) {
    int t4 = blockIdx.x*256 + threadIdx.x;
    int gi = t4 >> (oshift - 2);
    int oq = t4 & ((O >> 2) - 1);
    float4 m = mean[oq], is = istd[oq], g = ga[oq], b = be[oq];
    float4 mx = Mx[t4];
    float4 r;
    {
        float sc = is.x * g.x;
        float z = (mx.x - m.x)*sc + b.x; r.x = (z >= 0.f) ? z : NEG*z;
    }
    {
        float sc = is.y * g.y;
        float z = (mx.y - m.y)*sc + b.y; r.y = (z >= 0.f) ? z : NEG*z;
    }
    {
        float sc = is.z * g.z;
        float z = (mx.z - m.z)*sc + b.z; r.z = (z >= 0.f) ? z : NEG*z;
    }
    {
        float sc = is.w * g.w;
        float z = (mx.w - m.w)*sc + b.w; r.w = (z >= 0.f) ? z : NEG*z;
    }
    *(float4*)&XCAT[(size_t)gi*512 + choff + oq*4] = r;
}

// -------- final BN+lrelu with transposed write to d_out (B,512,N) --------
__global__ void finalize5(const float* __restrict__ P,
                          const float* __restrict__ ga, const float* __restrict__ be,
                          const float* __restrict__ mean, const float* __restrict__ istd,
                          float* __restrict__ out) {
    __shared__ float tile[32][33];
    int b = blockIdx.z, o0 = blockIdx.y * 32, n0 = blockIdx.x * 32;
    int tid = threadIdx.x;
    #pragma unroll
    for (int l = 0; l < 4; l++) {
        int e = tid + l*256;
        int nn = e >> 5, oo = e & 31;
        int o = o0 + oo;
        float v = P[(size_t)(b*NN + n0 + nn)*512 + o];
        v = (v - mean[o]) * istd[o] * ga[o] + be[o];
        v = (v >= 0.f) ? v : NEG*v;
        tile[oo][nn] = v;
    }
    __syncthreads();
    #pragma unroll
    for (int l = 0; l < 4; l++) {
        int e = tid + l*256;
        int oo = e >> 5, nn = e & 31;
        out[(size_t)b*512*NN + (size_t)(o0 + oo)*NN + n0 + nn] = tile[oo][nn];
    }
}

extern "C" void kernel_launch(void* const* d_in, const int* in_sizes, int n_in,
                              void* d_out, int out_size) {
    const float* x  = (const float*)d_in[0];
    const float* y  = (const float*)d_in[1];
    const float* w1 = (const float*)d_in[2];
    const float* w2 = (const float*)d_in[3];
    const float* w3 = (const float*)d_in[4];
    const float* w4 = (const float*)d_in[5];
    const float* w5 = (const float*)d_in[6];
    const float* g1 = (const float*)d_in[7];  const float* b1 = (const float*)d_in[8];
    const float* g2 = (const float*)d_in[9];  const float* b2 = (const float*)d_in[10];
    const float* g3 = (const float*)d_in[11]; const float* b3 = (const float*)d_in[12];
    const float* g4 = (const float*)d_in[13]; const float* b4 = (const float*)d_in[14];
    const float* g5 = (const float*)d_in[15]; const float* b5 = (const float*)d_in[16];
    float* out = (float*)d_out;

    float *yT, *ynT, *XCAT, *S, *P, *P5, *Q, *Wc, *part, *mean, *istd;
    int* idx;
    cudaGetSymbolAddress((void**)&yT,  g_yT);
    cudaGetSymbolAddress((void**)&ynT, g_ynT);
    cudaGetSymbolAddress((void**)&XCAT,g_XCAT);
    cudaGetSymbolAddress((void**)&S,   g_S);
    cudaGetSymbolAddress((void**)&P,   g_P);
    cudaGetSymbolAddress((void**)&P5,  g_P5);
    cudaGetSymbolAddress((void**)&Q,   g_Q);
    cudaGetSymbolAddress((void**)&Wc,  g_Wc);
    cudaGetSymbolAddress((void**)&idx, g_idx);
    cudaGetSymbolAddress((void**)&part,g_part);
    cudaGetSymbolAddress((void**)&mean,g_mean);
    cudaGetSymbolAddress((void**)&istd,g_istd);

    float* Mx = S;                 // S is free outside score/topk windows

    // fork-join side stream (host objects only; no device memory)
    cudaStream_t s1;
    cudaStreamCreateWithFlags(&s1, cudaStreamNonBlocking);
    cudaEvent_t evF, evP1, evP2, evP3, evQ4, evP5a, evF1, evF2, evF3;
    cudaEventCreateWithFlags(&evF,   cudaEventDisableTiming);
    cudaEventCreateWithFlags(&evP1,  cudaEventDisableTiming);
    cudaEventCreateWithFlags(&evP2,  cudaEventDisableTiming);
    cudaEventCreateWithFlags(&evP3,  cudaEventDisableTiming);
    cudaEventCreateWithFlags(&evQ4,  cudaEventDisableTiming);
    cudaEventCreateWithFlags(&evP5a, cudaEventDisableTiming);
    cudaEventCreateWithFlags(&evF1,  cudaEventDisableTiming);
    cudaEventCreateWithFlags(&evF2,  cudaEventDisableTiming);
    cudaEventCreateWithFlags(&evF3,  cudaEventDisableTiming);

    // fork
    cudaEventRecord(evF, 0);
    cudaStreamWaitEvent(s1, evF, 0);

    // side: y prep + weights + stage-1 P + EARLY stage-4 gathered operand
    prep_y<<<BN, 128, 0, s1>>>(y, yT, ynT);
    make_weights<<<226, 256, 0, s1>>>(w1, w2, w3, w4, Wc);
    pq1_kernel<<<BN*32/256, 256, 0, s1>>>(x, Wc, P);
    cudaEventRecord(evP1, s1);
    gemm128<<<dim3(2,64,1), 256, 0, s1>>>(128, 1, 0, 0, yT, 128, 0, w4, 256, 0, Q, 256, 0);

    // main: stage 1
    score1_topk<<<BN/8, 256>>>(x, idx);
    cudaStreamWaitEvent(0, evP1, 0);
    stats_mm_edge<<<dim3(64,8), 256>>>(P, 128, P+64, 128, idx, 64, 6, part, Mx);
    reduce_stats<<<8, 256>>>(64, 163840.f, part, mean, istd);
    finalize_mm4<<<BN*64/1024, 256>>>((float4*)Mx, 64, 6, 0,
        (const float4*)g1, (const float4*)b1, (const float4*)mean, (const float4*)istd, XCAT);
    cudaEventRecord(evF1, 0);

    // side: stage2 PQ gemm
    cudaStreamWaitEvent(s1, evF1, 0);
    gemm128<<<dim3(1,64,1), 256, 0, s1>>>(64, 1, 0, 0, XCAT, 512, 0, Wc+WS2, 64, 0, P, 128, 0);
    cudaEventRecord(evP2, s1);

    // main: stage 2
    gemm128<<<dim3(8,8,8), 256>>>(64, 1, 1, 0, XCAT, 512, NN*512, XCAT, 512, NN*512, S, NN, NN*NN);
    topk_warp<<<BN/8, 256>>>(S, idx);
    cudaStreamWaitEvent(0, evP2, 0);
    stats_mm_edge<<<dim3(64,8), 256>>>(P, 128, P+64, 128, idx, 64, 6, part, Mx);
    reduce_stats<<<8, 256>>>(64, 163840.f, part, mean, istd);
    finalize_mm4<<<BN*64/1024, 256>>>((float4*)Mx, 64, 6, 64,
        (const float4*)g2, (const float4*)b2, (const float4*)mean, (const float4*)istd, XCAT);
    cudaEventRecord(evF2, 0);

    // side: stage3 PQ gemm
    cudaStreamWaitEvent(s1, evF2, 0);
    gemm128<<<dim3(2,64,1), 256, 0, s1>>>(64, 1, 0, 0, XCAT + 64, 512, 0, Wc+WS3, 64, 0, P, 256, 0);
    cudaEventRecord(evP3, s1);

    // main: stage 3
    gemm128<<<dim3(8,8,8), 256>>>(64, 1, 1, 0, XCAT + 64, 512, NN*512, XCAT + 64, 512, NN*512, S, NN, NN*NN);
    topk_warp<<<BN/8, 256>>>(S, idx);
    cudaStreamWaitEvent(0, evP3, 0);
    stats_mm_edge<<<dim3(64,8), 256>>>(P, 256, P+128, 256, idx, 128, 7, part, Mx);
    reduce_stats<<<16, 256>>>(128, 163840.f, part, mean, istd);
    finalize_mm4<<<BN*128/1024, 256>>>((float4*)Mx, 128, 7, 128,
        (const float4*)g3, (const float4*)b3, (const float4*)mean, (const float4*)istd, XCAT);
    cudaEventRecord(evF3, 0);

    // side: stage4 center operand (Wc4 @ x3 -> P), then stage5 first K-half
    cudaStreamWaitEvent(s1, evF3, 0);
    gemm128<<<dim3(2,64,1), 256, 0, s1>>>(128, 1, 0, 0, XCAT + 128, 512, 0, Wc+WS4, 128, 0, P, 256, 0);
    cudaEventRecord(evQ4, s1);
    gemm128<<<dim3(4,64,1), 256, 0, s1>>>(256, 1, 0, 0, XCAT, 512, 0, w5, 512, 0, P5, 512, 0);
    cudaEventRecord(evP5a, s1);

    // main: stage 4 (gathered operand = Q [yT@w4], center operand = P [Wc4@x3])
    gemm128<<<dim3(8,8,8), 256>>>(128, 1, 0, 0, XCAT + 128, 512, NN*512, ynT, 128, NN*128,
                                  S, NN, NN*NN);
    topk_warp<<<BN/8, 256>>>(S, idx);
    cudaStreamWaitEvent(0, evQ4, 0);
    stats_mm_edge<<<dim3(64,8), 256>>>(Q, 256, P, 256, idx, 256, 8, part, Mx);
    reduce_stats<<<32, 256>>>(256, 163840.f, part, mean, istd);
    finalize_mm4<<<BN*256/1024, 256>>>((float4*)Mx, 256, 8, 256,
        (const float4*)g4, (const float4*)b4, (const float4*)mean, (const float4*)istd, XCAT);

    // main: stage 5 (second K-half accumulates onto side-computed first half)
    cudaStreamWaitEvent(0, evP5a, 0);
    gemm128<<<dim3(4,64,1), 256>>>(256, 1, 0, 1, XCAT + 256, 512, 0, w5 + 256, 512, 0, P5, 512, 0);
    stats_plain<<<dim3(64,8), 512>>>(P5, part);
    reduce_stats<<<64, 256>>>(512, 8192.f, part, mean, istd);
    finalize5<<<dim3(32,16,8), 256>>>(P5, g5, b5, mean, istd, out);
}

// round 15
// speedup vs baseline: 1.1052x; 1.0305x over previous
#include <cuda_runtime.h>
#include <math.h>

#define BB 8
#define NN 1024
#define BN (BB*NN)
#define KNN 20
#define NEG 0.2f
#define EPS 1e-5f
#define FULLM 0xffffffffu

// weight regions inside g_Wc
#define WS1 0        // stacked w1: 128 x 3   (384)
#define WS2 512      // stacked w2: 128 x 64  (8192)
#define WS3 9216     // stacked w3: 256 x 64  (16384)
#define WS4 26112    // diff   w4: 256 x 128  (32768)  end=58880

// -------- scratch (device globals; no allocation allowed) --------
__device__ float g_yT[BN*128];        // y transposed (B,M,128)
__device__ float g_ynT[BN*128];       // y normalized transposed
__device__ float g_XCAT[BN*512];      // concat of x1|x2|x3|x4 per point
__device__ float g_S[BB*NN*NN];       // score matrices (32MB); reused as Mx
__device__ float g_P[BN*512];         // PQ scratch
__device__ float g_P5[BN*512];        // stage5 pre-BN output (split-K accumulator)
__device__ float g_Q[BN*256];         // stage4 gathered operand (yT @ w4)
__device__ float g_Wc[64*1024];       // all prepped weights
__device__ int   g_idx[BN*KNN];       // knn indices
__device__ float g_part[2*1024*512];  // BN partial sums (1024 groups)
__device__ float g_mean[512];
__device__ float g_istd[512];

// -------- f32x2 packed helpers --------
__device__ __forceinline__ unsigned long long pack2(float x, float y) {
    unsigned long long r;
    asm("mov.b64 %0, {%1, %2};" : "=l"(r) : "f"(x), "f"(y));
    return r;
}
__device__ __forceinline__ void unpack2(unsigned long long v, float& x, float& y) {
    asm("mov.b64 {%0, %1}, %2;" : "=f"(x), "=f"(y) : "l"(v));
}
__device__ __forceinline__ void ffma2(unsigned long long& d,
                                      unsigned long long a, unsigned long long b) {
    asm("fma.rn.f32x2 %0, %1, %2, %0;" : "+l"(d) : "l"(a), "l"(b));
}

// -------- small prep kernels --------
__global__ void prep_y(const float* __restrict__ y, float* __restrict__ yT,
                       float* __restrict__ ynT) {
    int m = blockIdx.x;            // global point 0..8191
    int b = m >> 10, mm = m & 1023;
    int c = threadIdx.x;           // 128
    float v = y[((size_t)b*128 + c)*NN + mm];
    __shared__ float red[128];
    red[c] = v*v;
    __syncthreads();
    for (int s = 64; s > 0; s >>= 1) {
        if (c < s) red[c] += red[c+s];
        __syncthreads();
    }
    float nrm = sqrtf(red[0]);
    float sc = 1.0f / fmaxf(nrm, 1e-12f);
    yT [(size_t)m*128 + c] = v;
    ynT[(size_t)m*128 + c] = v * sc;
}

// one kernel prepping all weights
__global__ void make_weights(const float* __restrict__ w1, const float* __restrict__ w2,
                             const float* __restrict__ w3, const float* __restrict__ w4,
                             float* __restrict__ out) {
    int e = blockIdx.x*blockDim.x + threadIdx.x;
    if (e < 384) {
        int r = e / 3, c = e % 3;
        float v = (r < 64) ? w1[r*6 + c]
                           : w1[(r-64)*6 + 3 + c] - w1[(r-64)*6 + c];
        out[WS1 + e] = v;
    }
    int e2 = e - 384;
    if (e2 >= 0 && e2 < 8192) {
        int r = e2 >> 6, c = e2 & 63;
        float v = (r < 64) ? w2[r*128 + c]
                           : w2[(r-64)*128 + 64 + c] - w2[(r-64)*128 + c];
        out[WS2 + e2] = v;
    }
    int e3 = e2 - 8192;
    if (e3 >= 0 && e3 < 16384) {
        int r = e3 >> 6, c = e3 & 63;
        float v = (r < 128) ? w3[r*128 + c]
                            : w3[(r-128)*128 + 64 + c] - w3[(r-128)*128 + c];
        out[WS3 + e3] = v;
    }
    int e4 = e3 - 16384;
    if (e4 >= 0 && e4 < 32768) {
        int r = e4 >> 7, c = e4 & 127;
        out[WS4 + e4] = w4[r*256 + 128 + c] - w4[r*256 + c];
    }
}

// -------- stage-1 PQ: P[r][c] = sum_{k<3} x[b,k,n] * Wc1[c][k] -------------
__global__ void __launch_bounds__(256)
pq1_kernel(const float* __restrict__ x, const float* __restrict__ Wc,
           float* __restrict__ P) {
    __shared__ float w[384];
    for (int e = threadIdx.x; e < 384; e += 256) w[e] = Wc[WS1 + e];
    __syncthreads();
    int t = blockIdx.x*256 + threadIdx.x;
    int r = t >> 5;
    int cq = (t & 31) * 4;
    int b = r >> 10, n = r & 1023;
    float a0 = x[((size_t)b*3 + 0)*NN + n];
    float a1 = x[((size_t)b*3 + 1)*NN + n];
    float a2 = x[((size_t)b*3 + 2)*NN + n];
    float4 o;
    o.x = fmaf(a2, w[(cq+0)*3+2], fmaf(a1, w[(cq+0)*3+1], fmaf(a0, w[(cq+0)*3+0], 0.f)));
    o.y = fmaf(a2, w[(cq+1)*3+2], fmaf(a1, w[(cq+1)*3+1], fmaf(a0, w[(cq+1)*3+0], 0.f)));
    o.z = fmaf(a2, w[(cq+2)*3+2], fmaf(a1, w[(cq+2)*3+1], fmaf(a0, w[(cq+2)*3+0], 0.f)));
    o.w = fmaf(a2, w[(cq+3)*3+2], fmaf(a1, w[(cq+3)*3+1], fmaf(a0, w[(cq+3)*3+0], 0.f)));
    *(float4*)&P[(size_t)r*128 + cq] = o;
}

// -------- GEMM: C[r][c] (+)= sum_k A[r][k]*B[c][k] (+ selfbias) --------------
__global__ void __launch_bounds__(256, 2)
gemm128(int K, int vec, int selfbias, int accum,
        const float* __restrict__ A, int lda, int sA,
        const float* __restrict__ Bm, int ldb, int sB,
        float* __restrict__ C, int ldc, int sC) {
    __shared__ __align__(16) float As[2][16][132];
    __shared__ __align__(16) float Bs[2][16][132];
    int z = blockIdx.z;
    A  += (size_t)z * sA;
    Bm += (size_t)z * sB;
    C  += (size_t)z * sC;
    int row0 = blockIdx.y * 128, col0 = blockIdx.x * 128;
    int tid = threadIdx.x;
    int ty = tid >> 4, tx = tid & 15;

    unsigned long long acc[8][4];
    #pragma unroll
    for (int i = 0; i < 8; i++)
        #pragma unroll
        for (int j = 0; j < 4; j++) acc[i][j] = 0ULL;
    unsigned long long sq[4] = {0ULL, 0ULL, 0ULL, 0ULL};

    int nt = (K + 15) / 16;
    float ra[8], rb[8];
    float4 ra4[2], rb4[2];
    int vr = tid >> 2, vk = (tid & 3) * 4;

    if (vec) {
        #pragma unroll
        for (int l = 0; l < 2; l++) {
            ra4[l] = *(const float4*)&A [(size_t)(row0 + vr + l*64)*lda + vk];
            rb4[l] = *(const float4*)&Bm[(size_t)(col0 + vr + l*64)*ldb + vk];
        }
        #pragma unroll
        for (int l = 0; l < 2; l++) {
            int r = vr + l*64;
            As[0][vk+0][r] = ra4[l].x; As[0][vk+1][r] = ra4[l].y;
            As[0][vk+2][r] = ra4[l].z; As[0][vk+3][r] = ra4[l].w;
            Bs[0][vk+0][r] = rb4[l].x; Bs[0][vk+1][r] = rb4[l].y;
            Bs[0][vk+2][r] = rb4[l].z; Bs[0][vk+3][r] = rb4[l].w;
        }
    } else {
        #pragma unroll
        for (int l = 0; l < 8; l++) {
            int e = tid + l*256;
            int kk = e & 15, r = e >> 4;
            ra[l] = (kk < K) ? A [(size_t)(row0 + r)*lda + kk] : 0.f;
            rb[l] = (kk < K) ? Bm[(size_t)(col0 + r)*ldb + kk] : 0.f;
        }
        #pragma unroll
        for (int l = 0; l < 8; l++) {
            int e = tid + l*256;
            int kk = e & 15, r = e >> 4;
            As[0][kk][r] = ra[l];
            Bs[0][kk][r] = rb[l];
        }
    }
    __syncthreads();

    for (int t = 0; t < nt; t++) {
        int buf = t & 1;
        if (t + 1 < nt) {
            int k0 = (t + 1) * 16;
            if (vec) {
                #pragma unroll
                for (int l = 0; l < 2; l++) {
                    ra4[l] = *(const float4*)&A [(size_t)(row0 + vr + l*64)*lda + k0 + vk];
                    rb4[l] = *(const float4*)&Bm[(size_t)(col0 + vr + l*64)*ldb + k0 + vk];
                }
            } else {
                #pragma unroll
                for (int l = 0; l < 8; l++) {
                    int e = tid + l*256;
                    int kk = e & 15, r = e >> 4;
                    int gk = k0 + kk;
                    ra[l] = (gk < K) ? A [(size_t)(row0 + r)*lda + gk] : 0.f;
                    rb[l] = (gk < K) ? Bm[(size_t)(col0 + r)*ldb + gk] : 0.f;
                }
            }
        }
        #pragma unroll
        for (int kk = 0; kk < 16; kk++) {
            float4 a0 = *(const float4*)&As[buf][kk][ty*4];
            float4 a1 = *(const float4*)&As[buf][kk][ty*4 + 64];
            ulonglong2 bq0 = *(const ulonglong2*)&Bs[buf][kk][tx*4];
            ulonglong2 bq1 = *(const ulonglong2*)&Bs[buf][kk][tx*4 + 64];
            unsigned long long bb[4] = {bq0.x, bq0.y, bq1.x, bq1.y};
            float av[8] = {a0.x, a0.y, a0.z, a0.w, a1.x, a1.y, a1.z, a1.w};
            if (selfbias) {
                #pragma unroll
                for (int j = 0; j < 4; j++) ffma2(sq[j], bb[j], bb[j]);
            }
            #pragma unroll
            for (int i = 0; i < 8; i++) {
                unsigned long long ad = pack2(av[i], av[i]);
                #pragma unroll
                for (int j = 0; j < 4; j++) ffma2(acc[i][j], ad, bb[j]);
            }
        }
        if (t + 1 < nt) {
            int nb = (t + 1) & 1;
            if (vec) {
                #pragma unroll
                for (int l = 0; l < 2; l++) {
                    int r = vr + l*64;
                    As[nb][vk+0][r] = ra4[l].x; As[nb][vk+1][r] = ra4[l].y;
                    As[nb][vk+2][r] = ra4[l].z; As[nb][vk+3][r] = ra4[l].w;
                    Bs[nb][vk+0][r] = rb4[l].x; Bs[nb][vk+1][r] = rb4[l].y;
                    Bs[nb][vk+2][r] = rb4[l].z; Bs[nb][vk+3][r] = rb4[l].w;
                }
            } else {
                #pragma unroll
                for (int l = 0; l < 8; l++) {
                    int e = tid + l*256;
                    int kk = e & 15, r = e >> 4;
                    As[nb][kk][r] = ra[l];
                    Bs[nb][kk][r] = rb[l];
                }
            }
            __syncthreads();
        }
    }
    float bv[8] = {0,0,0,0,0,0,0,0};
    if (selfbias) {
        unpack2(sq[0], bv[0], bv[1]);
        unpack2(sq[1], bv[2], bv[3]);
        unpack2(sq[2], bv[4], bv[5]);
        unpack2(sq[3], bv[6], bv[7]);
        #pragma unroll
        for (int j = 0; j < 8; j++) bv[j] *= -0.5f;
    }
    #pragma unroll
    for (int i = 0; i < 8; i++) {
        int r = row0 + ((i >> 2) << 6) + ty*4 + (i & 3);
        int c0 = col0 + tx*4;
        int c1 = col0 + 64 + tx*4;
        float4 o0, o1;
        unpack2(acc[i][0], o0.x, o0.y);
        unpack2(acc[i][1], o0.z, o0.w);
        unpack2(acc[i][2], o1.x, o1.y);
        unpack2(acc[i][3], o1.z, o1.w);
        o0.x += bv[0]; o0.y += bv[1]; o0.z += bv[2]; o0.w += bv[3];
        o1.x += bv[4]; o1.y += bv[5]; o1.z += bv[6]; o1.w += bv[7];
        if (accum) {
            float4 p0 = *(float4*)&C[(size_t)r*ldc + c0];
            float4 p1 = *(float4*)&C[(size_t)r*ldc + c1];
            o0.x += p0.x; o0.y += p0.y; o0.z += p0.z; o0.w += p0.w;
            o1.x += p1.x; o1.y += p1.y; o1.z += p1.z; o1.w += p1.w;
        }
        *(float4*)&C[(size_t)r*ldc + c0] = o0;
        *(float4*)&C[(size_t)r*ldc + c1] = o1;
    }
}

// -------- warp top-20: global-second-max admission, sort only on final fill --
// Steady state: admit every head > S* (max of all lanes' seconds). Such heads
// exceed every non-head candidate and every non-admitted head, so the admitted
// set is exactly the global top-cnt (order in out[] irrelevant: it's a gather
// set). Guaranteed progress: the global max head strictly exceeds all seconds.
__device__ __forceinline__ void warp_topk20(float (&v)[32], int r, int lane,
                                            int* __restrict__ out) {
    // one-time head tournament (value + slot, ties -> lower slot)
    float h; int hs;
    {
        float tv16[16]; int tj16[16];
        #pragma unroll
        for (int j = 0; j < 16; j++) {
            bool t = v[2*j+1] > v[2*j];
            tv16[j] = t ? v[2*j+1] : v[2*j];
            tj16[j] = t ? 2*j+1 : 2*j;
        }
        float tv8[8]; int tj8[8];
        #pragma unroll
        for (int j = 0; j < 8; j++) {
            bool t = tv16[2*j+1] > tv16[2*j];
            tv8[j] = t ? tv16[2*j+1] : tv16[2*j];
            tj8[j] = t ? tj16[2*j+1] : tj16[2*j];
        }
        float tv4[4]; int tj4[4];
        #pragma unroll
        for (int j = 0; j < 4; j++) {
            bool t = tv8[2*j+1] > tv8[2*j];
            tv4[j] = t ? tv8[2*j+1] : tv8[2*j];
            tj4[j] = t ? tj8[2*j+1] : tj8[2*j];
        }
        float tv2[2]; int tj2[2];
        #pragma unroll
        for (int j = 0; j < 2; j++) {
            bool t = tv4[2*j+1] > tv4[2*j];
            tv2[j] = t ? tv4[2*j+1] : tv4[2*j];
            tj2[j] = t ? tj4[2*j+1] : tj4[2*j];
        }
        bool t0 = tv2[1] > tv2[0];
        h  = t0 ? tv2[1] : tv2[0];
        hs = t0 ? tj2[1] : tj2[0];
    }

    int done = 0;
    while (done < KNN) {
        // per-lane second (value + slot), strictly below head
        float s = -INFINITY; int ss = 0;
        #pragma unroll
        for (int j = 0; j < 32; j++) {
            float t = (v[j] < h) ? v[j] : -INFINITY;
            bool gt = t > s;
            s  = gt ? t : s;
            ss = gt ? j : ss;
        }

        // warp max of seconds
        float smax = s;
        #pragma unroll
        for (int off = 16; off; off >>= 1)
            smax = fmaxf(smax, __shfl_xor_sync(FULLM, smax, off));

        bool iadm = h > smax;
        unsigned adm = __ballot_sync(FULLM, iadm);
        int cnt = __popc(adm);
        int need = KNN - done;

        if (cnt <= need) {
            int pos = done + __popc(adm & ((1u << lane) - 1u));
            if (iadm) {
                out[(size_t)r*KNN + pos] = hs*32 + lane;
                h = s; hs = ss;         // promote
            }
            done += cnt;
        } else {
            // final fill: sort heads, take exactly `need` largest
            float hh = h;
            int   sl = lane;
            #pragma unroll
            for (int k = 2; k <= 32; k <<= 1) {
                #pragma unroll
                for (int j = k >> 1; j > 0; j >>= 1) {
                    float oh = __shfl_xor_sync(FULLM, hh, j);
                    int   ol = __shfl_xor_sync(FULLM, sl, j);
                    bool up = ((lane & k) == 0);
                    bool oless = (oh < hh) || (oh == hh && ol < sl);
                    bool takeMin = (((lane & j) == 0) == up);
                    bool pick_o = (oless == takeMin);
                    hh = pick_o ? oh : hh;
                    sl = pick_o ? ol : sl;
                }
            }
            int di = 31 - lane;
            int hsl = __shfl_sync(FULLM, hs, sl);
            if (di < need) out[(size_t)r*KNN + done + di] = hsl*32 + sl;
            done = KNN;
        }
    }
}

__global__ void __launch_bounds__(256)
topk_warp(const float* __restrict__ S, int* __restrict__ out) {
    int warp = threadIdx.x >> 5, lane = threadIdx.x & 31;
    int r = blockIdx.x * 8 + warp;
    const float* row = S + (size_t)r * NN;
    float v[32];
    #pragma unroll
    for (int j = 0; j < 32; j++) v[j] = row[j*32 + lane];
    warp_topk20(v, r, lane, out);
}

// stage 1 fused: reads x in native (B,3,N) layout
__global__ void __launch_bounds__(256)
score1_topk(const float* __restrict__ x, int* __restrict__ out) {
    int warp = threadIdx.x >> 5, lane = threadIdx.x & 31;
    int r = blockIdx.x * 8 + warp;
    int b = r >> 10, n = r & 1023;
    const float* xb = x + (size_t)b*3*NN;
    float cx = xb[n], cy = xb[NN + n], cz = xb[2*NN + n];
    float v[32];
    #pragma unroll
    for (int j = 0; j < 32; j++) {
        int col = j*32 + lane;
        float xj = xb[col], yj = xb[NN + col], zj = xb[2*NN + col];
        float half = -0.5f * (xj*xj + yj*yj + zj*zj);
        v[j] = fmaf(cx, xj, fmaf(cy, yj, fmaf(cz, zj, half)));
    }
    warp_topk20(v, r, lane, out);
}

// -------- single gather pass: BN stats + per-(point,channel) max --------
// grid (128, BB) = 1024 blocks, 8 points/block, 256 threads
__global__ void __launch_bounds__(256)
stats_mm_edge(const float* __restrict__ P, int ldp,
              const float* __restrict__ Q, int ldq,
              const int* __restrict__ idx, int O, int oshift,
              float* __restrict__ part,
              float* __restrict__ Mx) {
    __shared__ int sIdx[8*KNN];
    __shared__ float red1[256], red2[256];
    int b = blockIdx.y, i0 = blockIdx.x * 8;
    for (int e = threadIdx.x; e < 8*KNN; e += 256)
        sIdx[e] = idx[(size_t)(b*NN + i0)*KNN + e];
    __syncthreads();
    int o  = threadIdx.x & (O-1);
    int pp = threadIdx.x >> oshift;
    int PP = 256 >> oshift;
    float s1 = 0.f, s2 = 0.f;
    for (int ii = pp; ii < 8; ii += PP) {
        int gi = b*NN + i0 + ii;
        float qv = Q[(size_t)gi*ldq + o];
        float mx = -1e30f;
        float pv[KNN];
        #pragma unroll
        for (int k = 0; k < KNN; k++) {
            int j = sIdx[ii*KNN + k];
            pv[k] = P[(size_t)(b*NN + j)*ldp + o];
        }
        #pragma unroll
        for (int k = 0; k < KNN; k++) {
            float v = pv[k] + qv;
            s1 += v; s2 += v*v;
            mx = fmaxf(mx, v);
        }
        Mx[(size_t)gi*O + o] = mx;
    }
    red1[threadIdx.x] = s1; red2[threadIdx.x] = s2;
    __syncthreads();
    if (pp == 0) {
        for (int p = 1; p < PP; p++) { s1 += red1[o + p*O]; s2 += red2[o + p*O]; }
        int grp = blockIdx.y * 128 + blockIdx.x;   // < 1024
        part[(size_t)grp*O + o]          = s1;
        part[(size_t)(1024 + grp)*O + o] = s2;
    }
}

// grid (128, BB), 512 threads, 8 points/block
__global__ void stats_plain(const float* __restrict__ P, float* __restrict__ part) {
    int b = blockIdx.y, i0 = blockIdx.x * 8;
    int o = threadIdx.x;  // 512
    float s1 = 0.f, s2 = 0.f;
    #pragma unroll
    for (int ii = 0; ii < 8; ii++) {
        float v = P[(size_t)(b*NN + i0 + ii)*512 + o];
        s1 += v; s2 += v*v;
    }
    int grp = blockIdx.y * 128 + blockIdx.x;
    part[(size_t)grp*512 + o]          = s1;
    part[(size_t)(1024 + grp)*512 + o] = s2;
}

// warp-per-channel reduction over 1024 groups. grid = O/8, block = 256.
__global__ void __launch_bounds__(256)
reduce_stats(int O, float cnt, const float* __restrict__ part,
             float* __restrict__ mean, float* __restrict__ istd) {
    int warp = threadIdx.x >> 5, lane = threadIdx.x & 31;
    int o = blockIdx.x*8 + warp;
    float s1 = 0.f, s2 = 0.f;
    #pragma unroll
    for (int g = lane; g < 1024; g += 32) {
        s1 += part[(size_t)g*O + o];
        s2 += part[(size_t)(1024 + g)*O + o];
    }
    #pragma unroll
    for (int off = 16; off; off >>= 1) {
        s1 += __shfl_down_sync(FULLM, s1, off);
        s2 += __shfl_down_sync(FULLM, s2, off);
    }
    if (lane == 0) {
        float m = s1 / cnt;
        float var = s2 / cnt - m*m;
        mean[o] = m;
        istd[o] = rsqrtf(var + EPS);
    }
}

// -------- vectorized finalize from max (monotone BN+lrelu, scale>=0) --------
__global__ void __launch_bounds__(256)
finalize_mm4(const float4* __restrict__ Mx,
             int O, int oshift, int choff,
             const float4* __restrict__ ga, const float4* __restrict__ be,
             const float4* __restrict__ mean, const float4* __restrict__ istd,
             float* __restrict__ XCAT) {
    int t4 = blockIdx.x*256 + threadIdx.x;
    int gi = t4 >> (oshift - 2);
    int oq = t4 & ((O >> 2) - 1);
    float4 m = mean[oq], is = istd[oq], g = ga[oq], b = be[oq];
    float4 mx = Mx[t4];
    float4 r;
    {
        float sc = is.x * g.x;
        float z = (mx.x - m.x)*sc + b.x; r.x = (z >= 0.f) ? z : NEG*z;
    }
    {
        float sc = is.y * g.y;
        float z = (mx.y - m.y)*sc + b.y; r.y = (z >= 0.f) ? z : NEG*z;
    }
    {
        float sc = is.z * g.z;
        float z = (mx.z - m.z)*sc + b.z; r.z = (z >= 0.f) ? z : NEG*z;
    }
    {
        float sc = is.w * g.w;
        float z = (mx.w - m.w)*sc + b.w; r.w = (z >= 0.f) ? z : NEG*z;
    }
    *(float4*)&XCAT[(size_t)gi*512 + choff + oq*4] = r;
}

// -------- final BN+lrelu with transposed write to d_out (B,512,N) --------
__global__ void finalize5(const float* __restrict__ P,
                          const float* __restrict__ ga, const float* __restrict__ be,
                          const float* __restrict__ mean, const float* __restrict__ istd,
                          float* __restrict__ out) {
    __shared__ float tile[32][33];
    int b = blockIdx.z, o0 = blockIdx.y * 32, n0 = blockIdx.x * 32;
    int tid = threadIdx.x;
    #pragma unroll
    for (int l = 0; l < 4; l++) {
        int e = tid + l*256;
        int nn = e >> 5, oo = e & 31;
        int o = o0 + oo;
        float v = P[(size_t)(b*NN + n0 + nn)*512 + o];
        v = (v - mean[o]) * istd[o] * ga[o] + be[o];
        v = (v >= 0.f) ? v : NEG*v;
        tile[oo][nn] = v;
    }
    __syncthreads();
    #pragma unroll
    for (int l = 0; l < 4; l++) {
        int e = tid + l*256;
        int oo = e >> 5, nn = e & 31;
        out[(size_t)b*512*NN + (size_t)(o0 + oo)*NN + n0 + nn] = tile[oo][nn];
    }
}

extern "C" void kernel_launch(void* const* d_in, const int* in_sizes, int n_in,
                              void* d_out, int out_size) {
    const float* x  = (const float*)d_in[0];
    const float* y  = (const float*)d_in[1];
    const float* w1 = (const float*)d_in[2];
    const float* w2 = (const float*)d_in[3];
    const float* w3 = (const float*)d_in[4];
    const float* w4 = (const float*)d_in[5];
    const float* w5 = (const float*)d_in[6];
    const float* g1 = (const float*)d_in[7];  const float* b1 = (const float*)d_in[8];
    const float* g2 = (const float*)d_in[9];  const float* b2 = (const float*)d_in[10];
    const float* g3 = (const float*)d_in[11]; const float* b3 = (const float*)d_in[12];
    const float* g4 = (const float*)d_in[13]; const float* b4 = (const float*)d_in[14];
    const float* g5 = (const float*)d_in[15]; const float* b5 = (const float*)d_in[16];
    float* out = (float*)d_out;

    float *yT, *ynT, *XCAT, *S, *P, *P5, *Q, *Wc, *part, *mean, *istd;
    int* idx;
    cudaGetSymbolAddress((void**)&yT,  g_yT);
    cudaGetSymbolAddress((void**)&ynT, g_ynT);
    cudaGetSymbolAddress((void**)&XCAT,g_XCAT);
    cudaGetSymbolAddress((void**)&S,   g_S);
    cudaGetSymbolAddress((void**)&P,   g_P);
    cudaGetSymbolAddress((void**)&P5,  g_P5);
    cudaGetSymbolAddress((void**)&Q,   g_Q);
    cudaGetSymbolAddress((void**)&Wc,  g_Wc);
    cudaGetSymbolAddress((void**)&idx, g_idx);
    cudaGetSymbolAddress((void**)&part,g_part);
    cudaGetSymbolAddress((void**)&mean,g_mean);
    cudaGetSymbolAddress((void**)&istd,g_istd);

    float* Mx = S;                 // S is free outside score/topk windows

    // fork-join side stream (host objects only; no device memory)
    cudaStream_t s1;
    cudaStreamCreateWithFlags(&s1, cudaStreamNonBlocking);
    cudaEvent_t evF, evP1, evP2, evP3, evQ4, evP5a, evF1, evF2, evF3;
    cudaEventCreateWithFlags(&evF,   cudaEventDisableTiming);
    cudaEventCreateWithFlags(&evP1,  cudaEventDisableTiming);
    cudaEventCreateWithFlags(&evP2,  cudaEventDisableTiming);
    cudaEventCreateWithFlags(&evP3,  cudaEventDisableTiming);
    cudaEventCreateWithFlags(&evQ4,  cudaEventDisableTiming);
    cudaEventCreateWithFlags(&evP5a, cudaEventDisableTiming);
    cudaEventCreateWithFlags(&evF1,  cudaEventDisableTiming);
    cudaEventCreateWithFlags(&evF2,  cudaEventDisableTiming);
    cudaEventCreateWithFlags(&evF3,  cudaEventDisableTiming);

    // fork
    cudaEventRecord(evF, 0);
    cudaStreamWaitEvent(s1, evF, 0);

    // side: y prep + weights + stage-1 P + EARLY stage-4 gathered operand
    prep_y<<<BN, 128, 0, s1>>>(y, yT, ynT);
    make_weights<<<226, 256, 0, s1>>>(w1, w2, w3, w4, Wc);
    pq1_kernel<<<BN*32/256, 256, 0, s1>>>(x, Wc, P);
    cudaEventRecord(evP1, s1);
    gemm128<<<dim3(2,64,1), 256, 0, s1>>>(128, 1, 0, 0, yT, 128, 0, w4, 256, 0, Q, 256, 0);

    // main: stage 1
    score1_topk<<<BN/8, 256>>>(x, idx);
    cudaStreamWaitEvent(0, evP1, 0);
    stats_mm_edge<<<dim3(128,8), 256>>>(P, 128, P+64, 128, idx, 64, 6, part, Mx);
    reduce_stats<<<8, 256>>>(64, 163840.f, part, mean, istd);
    finalize_mm4<<<BN*64/1024, 256>>>((float4*)Mx, 64, 6, 0,
        (const float4*)g1, (const float4*)b1, (const float4*)mean, (const float4*)istd, XCAT);
    cudaEventRecord(evF1, 0);

    // side: stage2 PQ gemm
    cudaStreamWaitEvent(s1, evF1, 0);
    gemm128<<<dim3(1,64,1), 256, 0, s1>>>(64, 1, 0, 0, XCAT, 512, 0, Wc+WS2, 64, 0, P, 128, 0);
    cudaEventRecord(evP2, s1);

    // main: stage 2
    gemm128<<<dim3(8,8,8), 256>>>(64, 1, 1, 0, XCAT, 512, NN*512, XCAT, 512, NN*512, S, NN, NN*NN);
    topk_warp<<<BN/8, 256>>>(S, idx);
    cudaStreamWaitEvent(0, evP2, 0);
    stats_mm_edge<<<dim3(128,8), 256>>>(P, 128, P+64, 128, idx, 64, 6, part, Mx);
    reduce_stats<<<8, 256>>>(64, 163840.f, part, mean, istd);
    finalize_mm4<<<BN*64/1024, 256>>>((float4*)Mx, 64, 6, 64,
        (const float4*)g2, (const float4*)b2, (const float4*)mean, (const float4*)istd, XCAT);
    cudaEventRecord(evF2, 0);

    // side: stage3 PQ gemm
    cudaStreamWaitEvent(s1, evF2, 0);
    gemm128<<<dim3(2,64,1), 256, 0, s1>>>(64, 1, 0, 0, XCAT + 64, 512, 0, Wc+WS3, 64, 0, P, 256, 0);
    cudaEventRecord(evP3, s1);

    // main: stage 3
    gemm128<<<dim3(8,8,8), 256>>>(64, 1, 1, 0, XCAT + 64, 512, NN*512, XCAT + 64, 512, NN*512, S, NN, NN*NN);
    topk_warp<<<BN/8, 256>>>(S, idx);
    cudaStreamWaitEvent(0, evP3, 0);
    stats_mm_edge<<<dim3(128,8), 256>>>(P, 256, P+128, 256, idx, 128, 7, part, Mx);
    reduce_stats<<<16, 256>>>(128, 163840.f, part, mean, istd);
    finalize_mm4<<<BN*128/1024, 256>>>((float4*)Mx, 128, 7, 128,
        (const float4*)g3, (const float4*)b3, (const float4*)mean, (const float4*)istd, XCAT);
    cudaEventRecord(evF3, 0);

    // side: stage4 center operand (Wc4 @ x3 -> P), then stage5 first K-half
    cudaStreamWaitEvent(s1, evF3, 0);
    gemm128<<<dim3(2,64,1), 256, 0, s1>>>(128, 1, 0, 0, XCAT + 128, 512, 0, Wc+WS4, 128, 0, P, 256, 0);
    cudaEventRecord(evQ4, s1);
    gemm128<<<dim3(4,64,1), 256, 0, s1>>>(256, 1, 0, 0, XCAT, 512, 0, w5, 512, 0, P5, 512, 0);
    cudaEventRecord(evP5a, s1);

    // main: stage 4 (gathered operand = Q [yT@w4], center operand = P [Wc4@x3])
    gemm128<<<dim3(8,8,8), 256>>>(128, 1, 0, 0, XCAT + 128, 512, NN*512, ynT, 128, NN*128,
                                  S, NN, NN*NN);
    topk_warp<<<BN/8, 256>>>(S, idx);
    cudaStreamWaitEvent(0, evQ4, 0);
    stats_mm_edge<<<dim3(128,8), 256>>>(Q, 256, P, 256, idx, 256, 8, part, Mx);
    reduce_stats<<<32, 256>>>(256, 163840.f, part, mean, istd);
    finalize_mm4<<<BN*256/1024, 256>>>((float4*)Mx, 256, 8, 256,
        (const float4*)g4, (const float4*)b4, (const float4*)mean, (const float4*)istd, XCAT);

    // main: stage 5 (second K-half accumulates onto side-computed first half)
    cudaStreamWaitEvent(0, evP5a, 0);
    gemm128<<<dim3(4,64,1), 256>>>(256, 1, 0, 1, XCAT + 256, 512, 0, w5 + 256, 512, 0, P5, 512, 0);
    stats_plain<<<dim3(128,8), 512>>>(P5, part);
    reduce_stats<<<64, 256>>>(512, 8192.f, part, mean, istd);
    finalize5<<<dim3(32,16,8), 256>>>(P5, g5, b5, mean, istd, out);
}

// round 16
// speedup vs baseline: 1.1062x; 1.0009x over previous
#include <cuda_runtime.h>
#include <math.h>

#define BB 8
#define NN 1024
#define BN (BB*NN)
#define KNN 20
#define NEG 0.2f
#define EPS 1e-5f
#define FULLM 0xffffffffu

// weight regions inside g_Wc
#define WS1 0        // stacked w1: 128 x 3   (384)
#define WS2 512      // stacked w2: 128 x 64  (8192)
#define WS3 9216     // stacked w3: 256 x 64  (16384)
#define WS4 26112    // diff   w4: 256 x 128  (32768)  end=58880

// -------- scratch (device globals; no allocation allowed) --------
__device__ float g_yT[BN*128];        // y transposed (B,M,128)
__device__ float g_ynT[BN*128];       // y normalized transposed
__device__ float g_XCAT[BN*512];      // concat of x1|x2|x3|x4 per point
__device__ float g_S[BB*NN*NN];       // score matrices (32MB); reused as Mx
__device__ float g_P[BN*512];         // PQ scratch
__device__ float g_P5[BN*512];        // stage5 pre-BN output (split-K accumulator)
__device__ float g_Q[BN*256];         // stage4 gathered operand (yT @ w4)
__device__ float g_Wc[64*1024];       // all prepped weights
__device__ int   g_idx[BN*KNN];       // knn indices
__device__ float g_part[2*1024*512];  // BN partial sums (1024 groups)
__device__ float g_mean[512];
__device__ float g_istd[512];

// -------- f32x2 packed helpers --------
__device__ __forceinline__ unsigned long long pack2(float x, float y) {
    unsigned long long r;
    asm("mov.b64 %0, {%1, %2};" : "=l"(r) : "f"(x), "f"(y));
    return r;
}
__device__ __forceinline__ void unpack2(unsigned long long v, float& x, float& y) {
    asm("mov.b64 {%0, %1}, %2;" : "=f"(x), "=f"(y) : "l"(v));
}
__device__ __forceinline__ void ffma2(unsigned long long& d,
                                      unsigned long long a, unsigned long long b) {
    asm("fma.rn.f32x2 %0, %1, %2, %0;" : "+l"(d) : "l"(a), "l"(b));
}

// -------- small prep kernels --------
__global__ void prep_y(const float* __restrict__ y, float* __restrict__ yT,
                       float* __restrict__ ynT) {
    int m = blockIdx.x;            // global point 0..8191
    int b = m >> 10, mm = m & 1023;
    int c = threadIdx.x;           // 128
    float v = y[((size_t)b*128 + c)*NN + mm];
    __shared__ float red[128];
    red[c] = v*v;
    __syncthreads();
    for (int s = 64; s > 0; s >>= 1) {
        if (c < s) red[c] += red[c+s];
        __syncthreads();
    }
    float nrm = sqrtf(red[0]);
    float sc = 1.0f / fmaxf(nrm, 1e-12f);
    yT [(size_t)m*128 + c] = v;
    ynT[(size_t)m*128 + c] = v * sc;
}

// one kernel prepping all weights
__global__ void make_weights(const float* __restrict__ w1, const float* __restrict__ w2,
                             const float* __restrict__ w3, const float* __restrict__ w4,
                             float* __restrict__ out) {
    int e = blockIdx.x*blockDim.x + threadIdx.x;
    if (e < 384) {
        int r = e / 3, c = e % 3;
        float v = (r < 64) ? w1[r*6 + c]
                           : w1[(r-64)*6 + 3 + c] - w1[(r-64)*6 + c];
        out[WS1 + e] = v;
    }
    int e2 = e - 384;
    if (e2 >= 0 && e2 < 8192) {
        int r = e2 >> 6, c = e2 & 63;
        float v = (r < 64) ? w2[r*128 + c]
                           : w2[(r-64)*128 + 64 + c] - w2[(r-64)*128 + c];
        out[WS2 + e2] = v;
    }
    int e3 = e2 - 8192;
    if (e3 >= 0 && e3 < 16384) {
        int r = e3 >> 6, c = e3 & 63;
        float v = (r < 128) ? w3[r*128 + c]
                            : w3[(r-128)*128 + 64 + c] - w3[(r-128)*128 + c];
        out[WS3 + e3] = v;
    }
    int e4 = e3 - 16384;
    if (e4 >= 0 && e4 < 32768) {
        int r = e4 >> 7, c = e4 & 127;
        out[WS4 + e4] = w4[r*256 + 128 + c] - w4[r*256 + c];
    }
}

// -------- stage-1 PQ: P[r][c] = sum_{k<3} x[b,k,n] * Wc1[c][k] -------------
__global__ void __launch_bounds__(256)
pq1_kernel(const float* __restrict__ x, const float* __restrict__ Wc,
           float* __restrict__ P) {
    __shared__ float w[384];
    for (int e = threadIdx.x; e < 384; e += 256) w[e] = Wc[WS1 + e];
    __syncthreads();
    int t = blockIdx.x*256 + threadIdx.x;
    int r = t >> 5;
    int cq = (t & 31) * 4;
    int b = r >> 10, n = r & 1023;
    float a0 = x[((size_t)b*3 + 0)*NN + n];
    float a1 = x[((size_t)b*3 + 1)*NN + n];
    float a2 = x[((size_t)b*3 + 2)*NN + n];
    float4 o;
    o.x = fmaf(a2, w[(cq+0)*3+2], fmaf(a1, w[(cq+0)*3+1], fmaf(a0, w[(cq+0)*3+0], 0.f)));
    o.y = fmaf(a2, w[(cq+1)*3+2], fmaf(a1, w[(cq+1)*3+1], fmaf(a0, w[(cq+1)*3+0], 0.f)));
    o.z = fmaf(a2, w[(cq+2)*3+2], fmaf(a1, w[(cq+2)*3+1], fmaf(a0, w[(cq+2)*3+0], 0.f)));
    o.w = fmaf(a2, w[(cq+3)*3+2], fmaf(a1, w[(cq+3)*3+1], fmaf(a0, w[(cq+3)*3+0], 0.f)));
    *(float4*)&P[(size_t)r*128 + cq] = o;
}

// -------- GEMM: C[r][c] (+)= sum_k A[r][k]*B[c][k] (+ selfbias) --------------
__global__ void __launch_bounds__(256, 2)
gemm128(int K, int vec, int selfbias, int accum,
        const float* __restrict__ A, int lda, int sA,
        const float* __restrict__ Bm, int ldb, int sB,
        float* __restrict__ C, int ldc, int sC) {
    __shared__ __align__(16) float As[2][16][132];
    __shared__ __align__(16) float Bs[2][16][132];
    int z = blockIdx.z;
    A  += (size_t)z * sA;
    Bm += (size_t)z * sB;
    C  += (size_t)z * sC;
    int row0 = blockIdx.y * 128, col0 = blockIdx.x * 128;
    int tid = threadIdx.x;
    int ty = tid >> 4, tx = tid & 15;

    unsigned long long acc[8][4];
    #pragma unroll
    for (int i = 0; i < 8; i++)
        #pragma unroll
        for (int j = 0; j < 4; j++) acc[i][j] = 0ULL;
    unsigned long long sq[4] = {0ULL, 0ULL, 0ULL, 0ULL};

    int nt = (K + 15) / 16;
    float ra[8], rb[8];
    float4 ra4[2], rb4[2];
    int vr = tid >> 2, vk = (tid & 3) * 4;

    if (vec) {
        #pragma unroll
        for (int l = 0; l < 2; l++) {
            ra4[l] = *(const float4*)&A [(size_t)(row0 + vr + l*64)*lda + vk];
            rb4[l] = *(const float4*)&Bm[(size_t)(col0 + vr + l*64)*ldb + vk];
        }
        #pragma unroll
        for (int l = 0; l < 2; l++) {
            int r = vr + l*64;
            As[0][vk+0][r] = ra4[l].x; As[0][vk+1][r] = ra4[l].y;
            As[0][vk+2][r] = ra4[l].z; As[0][vk+3][r] = ra4[l].w;
            Bs[0][vk+0][r] = rb4[l].x; Bs[0][vk+1][r] = rb4[l].y;
            Bs[0][vk+2][r] = rb4[l].z; Bs[0][vk+3][r] = rb4[l].w;
        }
    } else {
        #pragma unroll
        for (int l = 0; l < 8; l++) {
            int e = tid + l*256;
            int kk = e & 15, r = e >> 4;
            ra[l] = (kk < K) ? A [(size_t)(row0 + r)*lda + kk] : 0.f;
            rb[l] = (kk < K) ? Bm[(size_t)(col0 + r)*ldb + kk] : 0.f;
        }
        #pragma unroll
        for (int l = 0; l < 8; l++) {
            int e = tid + l*256;
            int kk = e & 15, r = e >> 4;
            As[0][kk][r] = ra[l];
            Bs[0][kk][r] = rb[l];
        }
    }
    __syncthreads();

    for (int t = 0; t < nt; t++) {
        int buf = t & 1;
        if (t + 1 < nt) {
            int k0 = (t + 1) * 16;
            if (vec) {
                #pragma unroll
                for (int l = 0; l < 2; l++) {
                    ra4[l] = *(const float4*)&A [(size_t)(row0 + vr + l*64)*lda + k0 + vk];
                    rb4[l] = *(const float4*)&Bm[(size_t)(col0 + vr + l*64)*ldb + k0 + vk];
                }
            } else {
                #pragma unroll
                for (int l = 0; l < 8; l++) {
                    int e = tid + l*256;
                    int kk = e & 15, r = e >> 4;
                    int gk = k0 + kk;
                    ra[l] = (gk < K) ? A [(size_t)(row0 + r)*lda + gk] : 0.f;
                    rb[l] = (gk < K) ? Bm[(size_t)(col0 + r)*ldb + gk] : 0.f;
                }
            }
        }
        #pragma unroll
        for (int kk = 0; kk < 16; kk++) {
            float4 a0 = *(const float4*)&As[buf][kk][ty*4];
            float4 a1 = *(const float4*)&As[buf][kk][ty*4 + 64];
            ulonglong2 bq0 = *(const ulonglong2*)&Bs[buf][kk][tx*4];
            ulonglong2 bq1 = *(const ulonglong2*)&Bs[buf][kk][tx*4 + 64];
            unsigned long long bb[4] = {bq0.x, bq0.y, bq1.x, bq1.y};
            float av[8] = {a0.x, a0.y, a0.z, a0.w, a1.x, a1.y, a1.z, a1.w};
            if (selfbias) {
                #pragma unroll
                for (int j = 0; j < 4; j++) ffma2(sq[j], bb[j], bb[j]);
            }
            #pragma unroll
            for (int i = 0; i < 8; i++) {
                unsigned long long ad = pack2(av[i], av[i]);
                #pragma unroll
                for (int j = 0; j < 4; j++) ffma2(acc[i][j], ad, bb[j]);
            }
        }
        if (t + 1 < nt) {
            int nb = (t + 1) & 1;
            if (vec) {
                #pragma unroll
                for (int l = 0; l < 2; l++) {
                    int r = vr + l*64;
                    As[nb][vk+0][r] = ra4[l].x; As[nb][vk+1][r] = ra4[l].y;
                    As[nb][vk+2][r] = ra4[l].z; As[nb][vk+3][r] = ra4[l].w;
                    Bs[nb][vk+0][r] = rb4[l].x; Bs[nb][vk+1][r] = rb4[l].y;
                    Bs[nb][vk+2][r] = rb4[l].z; Bs[nb][vk+3][r] = rb4[l].w;
                }
            } else {
                #pragma unroll
                for (int l = 0; l < 8; l++) {
                    int e = tid + l*256;
                    int kk = e & 15, r = e >> 4;
                    As[nb][kk][r] = ra[l];
                    Bs[nb][kk][r] = rb[l];
                }
            }
            __syncthreads();
        }
    }
    float bv[8] = {0,0,0,0,0,0,0,0};
    if (selfbias) {
        unpack2(sq[0], bv[0], bv[1]);
        unpack2(sq[1], bv[2], bv[3]);
        unpack2(sq[2], bv[4], bv[5]);
        unpack2(sq[3], bv[6], bv[7]);
        #pragma unroll
        for (int j = 0; j < 8; j++) bv[j] *= -0.5f;
    }
    #pragma unroll
    for (int i = 0; i < 8; i++) {
        int r = row0 + ((i >> 2) << 6) + ty*4 + (i & 3);
        int c0 = col0 + tx*4;
        int c1 = col0 + 64 + tx*4;
        float4 o0, o1;
        unpack2(acc[i][0], o0.x, o0.y);
        unpack2(acc[i][1], o0.z, o0.w);
        unpack2(acc[i][2], o1.x, o1.y);
        unpack2(acc[i][3], o1.z, o1.w);
        o0.x += bv[0]; o0.y += bv[1]; o0.z += bv[2]; o0.w += bv[3];
        o1.x += bv[4]; o1.y += bv[5]; o1.z += bv[6]; o1.w += bv[7];
        if (accum) {
            float4 p0 = *(float4*)&C[(size_t)r*ldc + c0];
            float4 p1 = *(float4*)&C[(size_t)r*ldc + c1];
            o0.x += p0.x; o0.y += p0.y; o0.z += p0.z; o0.w += p0.w;
            o1.x += p1.x; o1.y += p1.y; o1.z += p1.z; o1.w += p1.w;
        }
        *(float4*)&C[(size_t)r*ldc + c0] = o0;
        *(float4*)&C[(size_t)r*ldc + c1] = o1;
    }
}

// -------- warp top-20: global-second-max admission, sort only on final fill --
// MODE selects the slot->column bijection:
//   MODE 0: col = slot*32 + lane              (scalar-load layout)
//   MODE 1: col = (slot>>2)*128 + lane*4 + (slot&3)  (float4-load layout)
template<int MODE>
__device__ __forceinline__ int tk_col(int slot, int ln) {
    return (MODE == 0) ? (slot*32 + ln)
                       : ((slot >> 2)*128 + ln*4 + (slot & 3));
}

template<int MODE>
__device__ __forceinline__ void warp_topk20(float (&v)[32], int r, int lane,
                                            int* __restrict__ out) {
    // one-time head tournament (value + slot, ties -> lower slot)
    float h; int hs;
    {
        float tv16[16]; int tj16[16];
        #pragma unroll
        for (int j = 0; j < 16; j++) {
            bool t = v[2*j+1] > v[2*j];
            tv16[j] = t ? v[2*j+1] : v[2*j];
            tj16[j] = t ? 2*j+1 : 2*j;
        }
        float tv8[8]; int tj8[8];
        #pragma unroll
        for (int j = 0; j < 8; j++) {
            bool t = tv16[2*j+1] > tv16[2*j];
            tv8[j] = t ? tv16[2*j+1] : tv16[2*j];
            tj8[j] = t ? tj16[2*j+1] : tj16[2*j];
        }
        float tv4[4]; int tj4[4];
        #pragma unroll
        for (int j = 0; j < 4; j++) {
            bool t = tv8[2*j+1] > tv8[2*j];
            tv4[j] = t ? tv8[2*j+1] : tv8[2*j];
            tj4[j] = t ? tj8[2*j+1] : tj8[2*j];
        }
        float tv2[2]; int tj2[2];
        #pragma unroll
        for (int j = 0; j < 2; j++) {
            bool t = tv4[2*j+1] > tv4[2*j];
            tv2[j] = t ? tv4[2*j+1] : tv4[2*j];
            tj2[j] = t ? tj4[2*j+1] : tj4[2*j];
        }
        bool t0 = tv2[1] > tv2[0];
        h  = t0 ? tv2[1] : tv2[0];
        hs = t0 ? tj2[1] : tj2[0];
    }

    int done = 0;
    while (done < KNN) {
        // per-lane second (value + slot), strictly below head
        float s = -INFINITY; int ss = 0;
        #pragma unroll
        for (int j = 0; j < 32; j++) {
            float t = (v[j] < h) ? v[j] : -INFINITY;
            bool gt = t > s;
            s  = gt ? t : s;
            ss = gt ? j : ss;
        }

        // warp max of seconds
        float smax = s;
        #pragma unroll
        for (int off = 16; off; off >>= 1)
            smax = fmaxf(smax, __shfl_xor_sync(FULLM, smax, off));

        bool iadm = h > smax;
        unsigned adm = __ballot_sync(FULLM, iadm);
        int cnt = __popc(adm);
        int need = KNN - done;

        if (cnt <= need) {
            int pos = done + __popc(adm & ((1u << lane) - 1u));
            if (iadm) {
                out[(size_t)r*KNN + pos] = tk_col<MODE>(hs, lane);
                h = s; hs = ss;         // promote
            }
            done += cnt;
        } else {
            // final fill: sort heads, take exactly `need` largest
            float hh = h;
            int   sl = lane;
            #pragma unroll
            for (int k = 2; k <= 32; k <<= 1) {
                #pragma unroll
                for (int j = k >> 1; j > 0; j >>= 1) {
                    float oh = __shfl_xor_sync(FULLM, hh, j);
                    int   ol = __shfl_xor_sync(FULLM, sl, j);
                    bool up = ((lane & k) == 0);
                    bool oless = (oh < hh) || (oh == hh && ol < sl);
                    bool takeMin = (((lane & j) == 0) == up);
                    bool pick_o = (oless == takeMin);
                    hh = pick_o ? oh : hh;
                    sl = pick_o ? ol : sl;
                }
            }
            int di = 31 - lane;
            int hsl = __shfl_sync(FULLM, hs, sl);
            if (di < need) out[(size_t)r*KNN + done + di] = tk_col<MODE>(hsl, sl);
            done = KNN;
        }
    }
}

__global__ void __launch_bounds__(256)
topk_warp(const float* __restrict__ S, int* __restrict__ out) {
    int warp = threadIdx.x >> 5, lane = threadIdx.x & 31;
    int r = blockIdx.x * 8 + warp;
    const float4* row4 = (const float4*)(S + (size_t)r * NN);
    float v[32];
    #pragma unroll
    for (int jf = 0; jf < 8; jf++) {
        float4 q = row4[jf*32 + lane];
        v[jf*4+0] = q.x; v[jf*4+1] = q.y; v[jf*4+2] = q.z; v[jf*4+3] = q.w;
    }
    warp_topk20<1>(v, r, lane, out);
}

// stage 1 fused: reads x in native (B,3,N) layout
__global__ void __launch_bounds__(256)
score1_topk(const float* __restrict__ x, int* __restrict__ out) {
    int warp = threadIdx.x >> 5, lane = threadIdx.x & 31;
    int r = blockIdx.x * 8 + warp;
    int b = r >> 10, n = r & 1023;
    const float* xb = x + (size_t)b*3*NN;
    float cx = xb[n], cy = xb[NN + n], cz = xb[2*NN + n];
    float v[32];
    #pragma unroll
    for (int j = 0; j < 32; j++) {
        int col = j*32 + lane;
        float xj = xb[col], yj = xb[NN + col], zj = xb[2*NN + col];
        float half = -0.5f * (xj*xj + yj*yj + zj*zj);
        v[j] = fmaf(cx, xj, fmaf(cy, yj, fmaf(cz, zj, half)));
    }
    warp_topk20<0>(v, r, lane, out);
}

// -------- single gather pass: BN stats + per-(point,channel) max --------
// grid (128, BB) = 1024 blocks, 8 points/block, 256 threads
__global__ void __launch_bounds__(256)
stats_mm_edge(const float* __restrict__ P, int ldp,
              const float* __restrict__ Q, int ldq,
              const int* __restrict__ idx, int O, int oshift,
              float* __restrict__ part,
              float* __restrict__ Mx) {
    __shared__ int sIdx[8*KNN];
    __shared__ float red1[256], red2[256];
    int b = blockIdx.y, i0 = blockIdx.x * 8;
    for (int e = threadIdx.x; e < 8*KNN; e += 256)
        sIdx[e] = idx[(size_t)(b*NN + i0)*KNN + e];
    __syncthreads();
    int o  = threadIdx.x & (O-1);
    int pp = threadIdx.x >> oshift;
    int PP = 256 >> oshift;
    float s1 = 0.f, s2 = 0.f;
    for (int ii = pp; ii < 8; ii += PP) {
        int gi = b*NN + i0 + ii;
        float qv = Q[(size_t)gi*ldq + o];
        float mx = -1e30f;
        float pv[KNN];
        #pragma unroll
        for (int k = 0; k < KNN; k++) {
            int j = sIdx[ii*KNN + k];
            pv[k] = P[(size_t)(b*NN + j)*ldp + o];
        }
        #pragma unroll
        for (int k = 0; k < KNN; k++) {
            float v = pv[k] + qv;
            s1 += v; s2 += v*v;
            mx = fmaxf(mx, v);
        }
        Mx[(size_t)gi*O + o] = mx;
    }
    red1[threadIdx.x] = s1; red2[threadIdx.x] = s2;
    __syncthreads();
    if (pp == 0) {
        for (int p = 1; p < PP; p++) { s1 += red1[o + p*O]; s2 += red2[o + p*O]; }
        int grp = blockIdx.y * 128 + blockIdx.x;   // < 1024
        part[(size_t)grp*O + o]          = s1;
        part[(size_t)(1024 + grp)*O + o] = s2;
    }
}

// grid (128, BB), 512 threads, 8 points/block
__global__ void stats_plain(const float* __restrict__ P, float* __restrict__ part) {
    int b = blockIdx.y, i0 = blockIdx.x * 8;
    int o = threadIdx.x;  // 512
    float s1 = 0.f, s2 = 0.f;
    #pragma unroll
    for (int ii = 0; ii < 8; ii++) {
        float v = P[(size_t)(b*NN + i0 + ii)*512 + o];
        s1 += v; s2 += v*v;
    }
    int grp = blockIdx.y * 128 + blockIdx.x;
    part[(size_t)grp*512 + o]          = s1;
    part[(size_t)(1024 + grp)*512 + o] = s2;
}

// warp-per-channel reduction over 1024 groups. grid = O/8, block = 256.
__global__ void __launch_bounds__(256)
reduce_stats(int O, float cnt, const float* __restrict__ part,
             float* __restrict__ mean, float* __restrict__ istd) {
    int warp = threadIdx.x >> 5, lane = threadIdx.x & 31;
    int o = blockIdx.x*8 + warp;
    float s1 = 0.f, s2 = 0.f;
    #pragma unroll
    for (int g = lane; g < 1024; g += 32) {
        s1 += part[(size_t)g*O + o];
        s2 += part[(size_t)(1024 + g)*O + o];
    }
    #pragma unroll
    for (int off = 16; off; off >>= 1) {
        s1 += __shfl_down_sync(FULLM, s1, off);
        s2 += __shfl_down_sync(FULLM, s2, off);
    }
    if (lane == 0) {
        float m = s1 / cnt;
        float var = s2 / cnt - m*m;
        mean[o] = m;
        istd[o] = rsqrtf(var + EPS);
    }
}

// -------- vectorized finalize from max (monotone BN+lrelu, scale>=0) --------
__global__ void __launch_bounds__(256)
finalize_mm4(const float4* __restrict__ Mx,
             int O, int oshift, int choff,
             const float4* __restrict__ ga, const float4* __restrict__ be,
             const float4* __restrict__ mean, const float4* __restrict__ istd,
             float* __restrict__ XCAT) {
    int t4 = blockIdx.x*256 + threadIdx.x;
    int gi = t4 >> (oshift - 2);
    int oq = t4 & ((O >> 2) - 1);
    float4 m = mean[oq], is = istd[oq], g = ga[oq], b = be[oq];
    float4 mx = Mx[t4];
    float4 r;
    {
        float sc = is.x * g.x;
        float z = (mx.x - m.x)*sc + b.x; r.x = (z >= 0.f) ? z : NEG*z;
    }
    {
        float sc = is.y * g.y;
        float z = (mx.y - m.y)*sc + b.y; r.y = (z >= 0.f) ? z : NEG*z;
    }
    {
        float sc = is.z * g.z;
        float z = (mx.z - m.z)*sc + b.z; r.z = (z >= 0.f) ? z : NEG*z;
    }
    {
        float sc = is.w * g.w;
        float z = (mx.w - m.w)*sc + b.w; r.w = (z >= 0.f) ? z : NEG*z;
    }
    *(float4*)&XCAT[(size_t)gi*512 + choff + oq*4] = r;
}

// -------- final BN+lrelu with transposed write to d_out (B,512,N) --------
__global__ void finalize5(const float* __restrict__ P,
                          const float* __restrict__ ga, const float* __restrict__ be,
                          const float* __restrict__ mean, const float* __restrict__ istd,
                          float* __restrict__ out) {
    __shared__ float tile[32][33];
    int b = blockIdx.z, o0 = blockIdx.y * 32, n0 = blockIdx.x * 32;
    int tid = threadIdx.x;
    #pragma unroll
    for (int l = 0; l < 4; l++) {
        int e = tid + l*256;
        int nn = e >> 5, oo = e & 31;
        int o = o0 + oo;
        float v = P[(size_t)(b*NN + n0 + nn)*512 + o];
        v = (v - mean[o]) * istd[o] * ga[o] + be[o];
        v = (v >= 0.f) ? v : NEG*v;
        tile[oo][nn] = v;
    }
    __syncthreads();
    #pragma unroll
    for (int l = 0; l < 4; l++) {
        int e = tid + l*256;
        int oo = e >> 5, nn = e & 31;
        out[(size_t)b*512*NN + (size_t)(o0 + oo)*NN + n0 + nn] = tile[oo][nn];
    }
}

extern "C" void kernel_launch(void* const* d_in, const int* in_sizes, int n_in,
                              void* d_out, int out_size) {
    const float* x  = (const float*)d_in[0];
    const float* y  = (const float*)d_in[1];
    const float* w1 = (const float*)d_in[2];
    const float* w2 = (const float*)d_in[3];
    const float* w3 = (const float*)d_in[4];
    const float* w4 = (const float*)d_in[5];
    const float* w5 = (const float*)d_in[6];
    const float* g1 = (const float*)d_in[7];  const float* b1 = (const float*)d_in[8];
    const float* g2 = (const float*)d_in[9];  const float* b2 = (const float*)d_in[10];
    const float* g3 = (const float*)d_in[11]; const float* b3 = (const float*)d_in[12];
    const float* g4 = (const float*)d_in[13]; const float* b4 = (const float*)d_in[14];
    const float* g5 = (const float*)d_in[15]; const float* b5 = (const float*)d_in[16];
    float* out = (float*)d_out;

    float *yT, *ynT, *XCAT, *S, *P, *P5, *Q, *Wc, *part, *mean, *istd;
    int* idx;
    cudaGetSymbolAddress((void**)&yT,  g_yT);
    cudaGetSymbolAddress((void**)&ynT, g_ynT);
    cudaGetSymbolAddress((void**)&XCAT,g_XCAT);
    cudaGetSymbolAddress((void**)&S,   g_S);
    cudaGetSymbolAddress((void**)&P,   g_P);
    cudaGetSymbolAddress((void**)&P5,  g_P5);
    cudaGetSymbolAddress((void**)&Q,   g_Q);
    cudaGetSymbolAddress((void**)&Wc,  g_Wc);
    cudaGetSymbolAddress((void**)&idx, g_idx);
    cudaGetSymbolAddress((void**)&part,g_part);
    cudaGetSymbolAddress((void**)&mean,g_mean);
    cudaGetSymbolAddress((void**)&istd,g_istd);

    float* Mx = S;                 // S is free outside score/topk windows

    // fork-join side stream (host objects only; no device memory)
    cudaStream_t s1;
    cudaStreamCreateWithFlags(&s1, cudaStreamNonBlocking);
    cudaEvent_t evF, evP1, evP2, evP3, evQ4, evP5a, evF1, evF2, evF3;
    cudaEventCreateWithFlags(&evF,   cudaEventDisableTiming);
    cudaEventCreateWithFlags(&evP1,  cudaEventDisableTiming);
    cudaEventCreateWithFlags(&evP2,  cudaEventDisableTiming);
    cudaEventCreateWithFlags(&evP3,  cudaEventDisableTiming);
    cudaEventCreateWithFlags(&evQ4,  cudaEventDisableTiming);
    cudaEventCreateWithFlags(&evP5a, cudaEventDisableTiming);
    cudaEventCreateWithFlags(&evF1,  cudaEventDisableTiming);
    cudaEventCreateWithFlags(&evF2,  cudaEventDisableTiming);
    cudaEventCreateWithFlags(&evF3,  cudaEventDisableTiming);

    // fork
    cudaEventRecord(evF, 0);
    cudaStreamWaitEvent(s1, evF, 0);

    // side: y prep + weights + stage-1 P + EARLY stage-4 gathered operand
    prep_y<<<BN, 128, 0, s1>>>(y, yT, ynT);
    make_weights<<<226, 256, 0, s1>>>(w1, w2, w3, w4, Wc);
    pq1_kernel<<<BN*32/256, 256, 0, s1>>>(x, Wc, P);
    cudaEventRecord(evP1, s1);
    gemm128<<<dim3(2,64,1), 256, 0, s1>>>(128, 1, 0, 0, yT, 128, 0, w4, 256, 0, Q, 256, 0);

    // main: stage 1
    score1_topk<<<BN/8, 256>>>(x, idx);
    cudaStreamWaitEvent(0, evP1, 0);
    stats_mm_edge<<<dim3(128,8), 256>>>(P, 128, P+64, 128, idx, 64, 6, part, Mx);
    reduce_stats<<<8, 256>>>(64, 163840.f, part, mean, istd);
    finalize_mm4<<<BN*64/1024, 256>>>((float4*)Mx, 64, 6, 0,
        (const float4*)g1, (const float4*)b1, (const float4*)mean, (const float4*)istd, XCAT);
    cudaEventRecord(evF1, 0);

    // side: stage2 PQ gemm
    cudaStreamWaitEvent(s1, evF1, 0);
    gemm128<<<dim3(1,64,1), 256, 0, s1>>>(64, 1, 0, 0, XCAT, 512, 0, Wc+WS2, 64, 0, P, 128, 0);
    cudaEventRecord(evP2, s1);

    // main: stage 2
    gemm128<<<dim3(8,8,8), 256>>>(64, 1, 1, 0, XCAT, 512, NN*512, XCAT, 512, NN*512, S, NN, NN*NN);
    topk_warp<<<BN/8, 256>>>(S, idx);
    cudaStreamWaitEvent(0, evP2, 0);
    stats_mm_edge<<<dim3(128,8), 256>>>(P, 128, P+64, 128, idx, 64, 6, part, Mx);
    reduce_stats<<<8, 256>>>(64, 163840.f, part, mean, istd);
    finalize_mm4<<<BN*64/1024, 256>>>((float4*)Mx, 64, 6, 64,
        (const float4*)g2, (const float4*)b2, (const float4*)mean, (const float4*)istd, XCAT);
    cudaEventRecord(evF2, 0);

    // side: stage3 PQ gemm
    cudaStreamWaitEvent(s1, evF2, 0);
    gemm128<<<dim3(2,64,1), 256, 0, s1>>>(64, 1, 0, 0, XCAT + 64, 512, 0, Wc+WS3, 64, 0, P, 256, 0);
    cudaEventRecord(evP3, s1);

    // main: stage 3
    gemm128<<<dim3(8,8,8), 256>>>(64, 1, 1, 0, XCAT + 64, 512, NN*512, XCAT + 64, 512, NN*512, S, NN, NN*NN);
    topk_warp<<<BN/8, 256>>>(S, idx);
    cudaStreamWaitEvent(0, evP3, 0);
    stats_mm_edge<<<dim3(128,8), 256>>>(P, 256, P+128, 256, idx, 128, 7, part, Mx);
    reduce_stats<<<16, 256>>>(128, 163840.f, part, mean, istd);
    finalize_mm4<<<BN*128/1024, 256>>>((float4*)Mx, 128, 7, 128,
        (const float4*)g3, (const float4*)b3, (const float4*)mean, (const float4*)istd, XCAT);
    cudaEventRecord(evF3, 0);

    // side: stage4 center operand (Wc4 @ x3 -> P), then stage5 first K-half
    cudaStreamWaitEvent(s1, evF3, 0);
    gemm128<<<dim3(2,64,1), 256, 0, s1>>>(128, 1, 0, 0, XCAT + 128, 512, 0, Wc+WS4, 128, 0, P, 256, 0);
    cudaEventRecord(evQ4, s1);
    gemm128<<<dim3(4,64,1), 256, 0, s1>>>(256, 1, 0, 0, XCAT, 512, 0, w5, 512, 0, P5, 512, 0);
    cudaEventRecord(evP5a, s1);

    // main: stage 4 (gathered operand = Q [yT@w4], center operand = P [Wc4@x3])
    gemm128<<<dim3(8,8,8), 256>>>(128, 1, 0, 0, XCAT + 128, 512, NN*512, ynT, 128, NN*128,
                                  S, NN, NN*NN);
    topk_warp<<<BN/8, 256>>>(S, idx);
    cudaStreamWaitEvent(0, evQ4, 0);
    stats_mm_edge<<<dim3(128,8), 256>>>(Q, 256, P, 256, idx, 256, 8, part, Mx);
    reduce_stats<<<32, 256>>>(256, 163840.f, part, mean, istd);
    finalize_mm4<<<BN*256/1024, 256>>>((float4*)Mx, 256, 8, 256,
        (const float4*)g4, (const float4*)b4, (const float4*)mean, (const float4*)istd, XCAT);

    // main: stage 5 (second K-half accumulates onto side-computed first half)
    cudaStreamWaitEvent(0, evP5a, 0);
    gemm128<<<dim3(4,64,1), 256>>>(256, 1, 0, 1, XCAT + 256, 512, 0, w5 + 256, 512, 0, P5, 512, 0);
    stats_plain<<<dim3(128,8), 512>>>(P5, part);
    reduce_stats<<<64, 256>>>(512, 8192.f, part, mean, istd);
    finalize5<<<dim3(32,16,8), 256>>>(P5, g5, b5, mean, istd, out);
}

// round 17
// speedup vs baseline: 1.1110x; 1.0043x over previous
#include <cuda_runtime.h>
#include <math.h>

#define BB 8
#define NN 1024
#define BN (BB*NN)
#define KNN 20
#define NEG 0.2f
#define EPS 1e-5f
#define FULLM 0xffffffffu

// weight regions inside g_Wc
#define WS1 0        // stacked w1: 128 x 3   (384)
#define WS2 512      // stacked w2: 128 x 64  (8192)
#define WS3 9216     // stacked w3: 256 x 64  (16384)
#define WS4 26112    // diff   w4: 256 x 128  (32768)  end=58880

// -------- scratch (device globals; no allocation allowed) --------
__device__ float g_yT[BN*128];        // y transposed (B,M,128)
__device__ float g_ynT[BN*128];       // y normalized transposed
__device__ float g_XCAT[BN*512];      // concat of x1|x2|x3|x4 per point
__device__ float g_S[BB*NN*NN];       // score matrices (32MB); reused as Mx
__device__ float g_P[BN*512];         // PQ scratch
__device__ float g_P5[BN*512];        // stage5 pre-BN output (split-K accumulator)
__device__ float g_Q[BN*256];         // stage4 gathered operand (yT @ w4)
__device__ float g_Wc[64*1024];       // all prepped weights
__device__ int   g_idx[BN*KNN];       // knn indices
__device__ float g_part[2*1024*512];  // BN partial sums (1024 groups)
__device__ float g_mean[512];
__device__ float g_istd[512];

// -------- f32x2 packed helpers --------
__device__ __forceinline__ unsigned long long pack2(float x, float y) {
    unsigned long long r;
    asm("mov.b64 %0, {%1, %2};" : "=l"(r) : "f"(x), "f"(y));
    return r;
}
__device__ __forceinline__ void unpack2(unsigned long long v, float& x, float& y) {
    asm("mov.b64 {%0, %1}, %2;" : "=f"(x), "=f"(y) : "l"(v));
}
__device__ __forceinline__ void ffma2(unsigned long long& d,
                                      unsigned long long a, unsigned long long b) {
    asm("fma.rn.f32x2 %0, %1, %2, %0;" : "+l"(d) : "l"(a), "l"(b));
}

// -------- small prep kernels --------
__global__ void prep_y(const float* __restrict__ y, float* __restrict__ yT,
                       float* __restrict__ ynT) {
    int m = blockIdx.x;            // global point 0..8191
    int b = m >> 10, mm = m & 1023;
    int c = threadIdx.x;           // 128
    float v = y[((size_t)b*128 + c)*NN + mm];
    __shared__ float red[128];
    red[c] = v*v;
    __syncthreads();
    for (int s = 64; s > 0; s >>= 1) {
        if (c < s) red[c] += red[c+s];
        __syncthreads();
    }
    float nrm = sqrtf(red[0]);
    float sc = 1.0f / fmaxf(nrm, 1e-12f);
    yT [(size_t)m*128 + c] = v;
    ynT[(size_t)m*128 + c] = v * sc;
}

// one kernel prepping all weights
__global__ void make_weights(const float* __restrict__ w1, const float* __restrict__ w2,
                             const float* __restrict__ w3, const float* __restrict__ w4,
                             float* __restrict__ out) {
    int e = blockIdx.x*blockDim.x + threadIdx.x;
    if (e < 384) {
        int r = e / 3, c = e % 3;
        float v = (r < 64) ? w1[r*6 + c]
                           : w1[(r-64)*6 + 3 + c] - w1[(r-64)*6 + c];
        out[WS1 + e] = v;
    }
    int e2 = e - 384;
    if (e2 >= 0 && e2 < 8192) {
        int r = e2 >> 6, c = e2 & 63;
        float v = (r < 64) ? w2[r*128 + c]
                           : w2[(r-64)*128 + 64 + c] - w2[(r-64)*128 + c];
        out[WS2 + e2] = v;
    }
    int e3 = e2 - 8192;
    if (e3 >= 0 && e3 < 16384) {
        int r = e3 >> 6, c = e3 & 63;
        float v = (r < 128) ? w3[r*128 + c]
                            : w3[(r-128)*128 + 64 + c] - w3[(r-128)*128 + c];
        out[WS3 + e3] = v;
    }
    int e4 = e3 - 16384;
    if (e4 >= 0 && e4 < 32768) {
        int r = e4 >> 7, c = e4 & 127;
        out[WS4 + e4] = w4[r*256 + 128 + c] - w4[r*256 + c];
    }
}

// -------- stage-1 PQ: P[r][c] = sum_{k<3} x[b,k,n] * Wc1[c][k] -------------
__global__ void __launch_bounds__(256)
pq1_kernel(const float* __restrict__ x, const float* __restrict__ Wc,
           float* __restrict__ P) {
    __shared__ float w[384];
    for (int e = threadIdx.x; e < 384; e += 256) w[e] = Wc[WS1 + e];
    __syncthreads();
    int t = blockIdx.x*256 + threadIdx.x;
    int r = t >> 5;
    int cq = (t & 31) * 4;
    int b = r >> 10, n = r & 1023;
    float a0 = x[((size_t)b*3 + 0)*NN + n];
    float a1 = x[((size_t)b*3 + 1)*NN + n];
    float a2 = x[((size_t)b*3 + 2)*NN + n];
    float4 o;
    o.x = fmaf(a2, w[(cq+0)*3+2], fmaf(a1, w[(cq+0)*3+1], fmaf(a0, w[(cq+0)*3+0], 0.f)));
    o.y = fmaf(a2, w[(cq+1)*3+2], fmaf(a1, w[(cq+1)*3+1], fmaf(a0, w[(cq+1)*3+0], 0.f)));
    o.z = fmaf(a2, w[(cq+2)*3+2], fmaf(a1, w[(cq+2)*3+1], fmaf(a0, w[(cq+2)*3+0], 0.f)));
    o.w = fmaf(a2, w[(cq+3)*3+2], fmaf(a1, w[(cq+3)*3+1], fmaf(a0, w[(cq+3)*3+0], 0.f)));
    *(float4*)&P[(size_t)r*128 + cq] = o;
}

// -------- GEMM: C[r][c] (+)= sum_k A[r][k]*B[c][k] (+ selfbias) --------------
__global__ void __launch_bounds__(256, 2)
gemm128(int K, int vec, int selfbias, int accum,
        const float* __restrict__ A, int lda, int sA,
        const float* __restrict__ Bm, int ldb, int sB,
        float* __restrict__ C, int ldc, int sC) {
    __shared__ __align__(16) float As[2][16][132];
    __shared__ __align__(16) float Bs[2][16][132];
    int z = blockIdx.z;
    A  += (size_t)z * sA;
    Bm += (size_t)z * sB;
    C  += (size_t)z * sC;
    int row0 = blockIdx.y * 128, col0 = blockIdx.x * 128;
    int tid = threadIdx.x;
    int ty = tid >> 4, tx = tid & 15;

    unsigned long long acc[8][4];
    #pragma unroll
    for (int i = 0; i < 8; i++)
        #pragma unroll
        for (int j = 0; j < 4; j++) acc[i][j] = 0ULL;
    unsigned long long sq[4] = {0ULL, 0ULL, 0ULL, 0ULL};

    int nt = (K + 15) / 16;
    float ra[8], rb[8];
    float4 ra4[2], rb4[2];
    int vr = tid >> 2, vk = (tid & 3) * 4;

    if (vec) {
        #pragma unroll
        for (int l = 0; l < 2; l++) {
            ra4[l] = *(const float4*)&A [(size_t)(row0 + vr + l*64)*lda + vk];
            rb4[l] = *(const float4*)&Bm[(size_t)(col0 + vr + l*64)*ldb + vk];
        }
        #pragma unroll
        for (int l = 0; l < 2; l++) {
            int r = vr + l*64;
            As[0][vk+0][r] = ra4[l].x; As[0][vk+1][r] = ra4[l].y;
            As[0][vk+2][r] = ra4[l].z; As[0][vk+3][r] = ra4[l].w;
            Bs[0][vk+0][r] = rb4[l].x; Bs[0][vk+1][r] = rb4[l].y;
            Bs[0][vk+2][r] = rb4[l].z; Bs[0][vk+3][r] = rb4[l].w;
        }
    } else {
        #pragma unroll
        for (int l = 0; l < 8; l++) {
            int e = tid + l*256;
            int kk = e & 15, r = e >> 4;
            ra[l] = (kk < K) ? A [(size_t)(row0 + r)*lda + kk] : 0.f;
            rb[l] = (kk < K) ? Bm[(size_t)(col0 + r)*ldb + kk] : 0.f;
        }
        #pragma unroll
        for (int l = 0; l < 8; l++) {
            int e = tid + l*256;
            int kk = e & 15, r = e >> 4;
            As[0][kk][r] = ra[l];
            Bs[0][kk][r] = rb[l];
        }
    }
    __syncthreads();

    for (int t = 0; t < nt; t++) {
        int buf = t & 1;
        if (t + 1 < nt) {
            int k0 = (t + 1) * 16;
            if (vec) {
                #pragma unroll
                for (int l = 0; l < 2; l++) {
                    ra4[l] = *(const float4*)&A [(size_t)(row0 + vr + l*64)*lda + k0 + vk];
                    rb4[l] = *(const float4*)&Bm[(size_t)(col0 + vr + l*64)*ldb + k0 + vk];
                }
            } else {
                #pragma unroll
                for (int l = 0; l < 8; l++) {
                    int e = tid + l*256;
                    int kk = e & 15, r = e >> 4;
                    int gk = k0 + kk;
                    ra[l] = (gk < K) ? A [(size_t)(row0 + r)*lda + gk] : 0.f;
                    rb[l] = (gk < K) ? Bm[(size_t)(col0 + r)*ldb + gk] : 0.f;
                }
            }
        }
        #pragma unroll
        for (int kk = 0; kk < 16; kk++) {
            float4 a0 = *(const float4*)&As[buf][kk][ty*4];
            float4 a1 = *(const float4*)&As[buf][kk][ty*4 + 64];
            ulonglong2 bq0 = *(const ulonglong2*)&Bs[buf][kk][tx*4];
            ulonglong2 bq1 = *(const ulonglong2*)&Bs[buf][kk][tx*4 + 64];
            unsigned long long bb[4] = {bq0.x, bq0.y, bq1.x, bq1.y};
            float av[8] = {a0.x, a0.y, a0.z, a0.w, a1.x, a1.y, a1.z, a1.w};
            if (selfbias) {
                #pragma unroll
                for (int j = 0; j < 4; j++) ffma2(sq[j], bb[j], bb[j]);
            }
            #pragma unroll
            for (int i = 0; i < 8; i++) {
                unsigned long long ad = pack2(av[i], av[i]);
                #pragma unroll
                for (int j = 0; j < 4; j++) ffma2(acc[i][j], ad, bb[j]);
            }
        }
        if (t + 1 < nt) {
            int nb = (t + 1) & 1;
            if (vec) {
                #pragma unroll
                for (int l = 0; l < 2; l++) {
                    int r = vr + l*64;
                    As[nb][vk+0][r] = ra4[l].x; As[nb][vk+1][r] = ra4[l].y;
                    As[nb][vk+2][r] = ra4[l].z; As[nb][vk+3][r] = ra4[l].w;
                    Bs[nb][vk+0][r] = rb4[l].x; Bs[nb][vk+1][r] = rb4[l].y;
                    Bs[nb][vk+2][r] = rb4[l].z; Bs[nb][vk+3][r] = rb4[l].w;
                }
            } else {
                #pragma unroll
                for (int l = 0; l < 8; l++) {
                    int e = tid + l*256;
                    int kk = e & 15, r = e >> 4;
                    As[nb][kk][r] = ra[l];
                    Bs[nb][kk][r] = rb[l];
                }
            }
            __syncthreads();
        }
    }
    float bv[8] = {0,0,0,0,0,0,0,0};
    if (selfbias) {
        unpack2(sq[0], bv[0], bv[1]);
        unpack2(sq[1], bv[2], bv[3]);
        unpack2(sq[2], bv[4], bv[5]);
        unpack2(sq[3], bv[6], bv[7]);
        #pragma unroll
        for (int j = 0; j < 8; j++) bv[j] *= -0.5f;
    }
    #pragma unroll
    for (int i = 0; i < 8; i++) {
        int r = row0 + ((i >> 2) << 6) + ty*4 + (i & 3);
        int c0 = col0 + tx*4;
        int c1 = col0 + 64 + tx*4;
        float4 o0, o1;
        unpack2(acc[i][0], o0.x, o0.y);
        unpack2(acc[i][1], o0.z, o0.w);
        unpack2(acc[i][2], o1.x, o1.y);
        unpack2(acc[i][3], o1.z, o1.w);
        o0.x += bv[0]; o0.y += bv[1]; o0.z += bv[2]; o0.w += bv[3];
        o1.x += bv[4]; o1.y += bv[5]; o1.z += bv[6]; o1.w += bv[7];
        if (accum) {
            float4 p0 = *(float4*)&C[(size_t)r*ldc + c0];
            float4 p1 = *(float4*)&C[(size_t)r*ldc + c1];
            o0.x += p0.x; o0.y += p0.y; o0.z += p0.z; o0.w += p0.w;
            o1.x += p1.x; o1.y += p1.y; o1.z += p1.z; o1.w += p1.w;
        }
        *(float4*)&C[(size_t)r*ldc + c0] = o0;
        *(float4*)&C[(size_t)r*ldc + c1] = o1;
    }
}

// -------- warp top-20: global-second-max admission, sort only on final fill --
// MODE selects the slot->column bijection:
//   MODE 0: col = slot*32 + lane              (scalar-load layout)
//   MODE 1: col = (slot>>2)*128 + lane*4 + (slot&3)  (float4-load layout)
template<int MODE>
__device__ __forceinline__ int tk_col(int slot, int ln) {
    return (MODE == 0) ? (slot*32 + ln)
                       : ((slot >> 2)*128 + ln*4 + (slot & 3));
}

template<int MODE>
__device__ __forceinline__ void warp_topk20(float (&v)[32], int r, int lane,
                                            int* __restrict__ out) {
    // one-time head tournament (value + slot, ties -> lower slot)
    float h; int hs;
    {
        float tv16[16]; int tj16[16];
        #pragma unroll
        for (int j = 0; j < 16; j++) {
            bool t = v[2*j+1] > v[2*j];
            tv16[j] = t ? v[2*j+1] : v[2*j];
            tj16[j] = t ? 2*j+1 : 2*j;
        }
        float tv8[8]; int tj8[8];
        #pragma unroll
        for (int j = 0; j < 8; j++) {
            bool t = tv16[2*j+1] > tv16[2*j];
            tv8[j] = t ? tv16[2*j+1] : tv16[2*j];
            tj8[j] = t ? tj16[2*j+1] : tj16[2*j];
        }
        float tv4[4]; int tj4[4];
        #pragma unroll
        for (int j = 0; j < 4; j++) {
            bool t = tv8[2*j+1] > tv8[2*j];
            tv4[j] = t ? tv8[2*j+1] : tv8[2*j];
            tj4[j] = t ? tj8[2*j+1] : tj8[2*j];
        }
        float tv2[2]; int tj2[2];
        #pragma unroll
        for (int j = 0; j < 2; j++) {
            bool t = tv4[2*j+1] > tv4[2*j];
            tv2[j] = t ? tv4[2*j+1] : tv4[2*j];
            tj2[j] = t ? tj4[2*j+1] : tj4[2*j];
        }
        bool t0 = tv2[1] > tv2[0];
        h  = t0 ? tv2[1] : tv2[0];
        hs = t0 ? tj2[1] : tj2[0];
    }

    int done = 0;
    while (done < KNN) {
        // per-lane second (value + slot), strictly below head
        float s = -INFINITY; int ss = 0;
        #pragma unroll
        for (int j = 0; j < 32; j++) {
            float t = (v[j] < h) ? v[j] : -INFINITY;
            bool gt = t > s;
            s  = gt ? t : s;
            ss = gt ? j : ss;
        }

        // warp max of seconds
        float smax = s;
        #pragma unroll
        for (int off = 16; off; off >>= 1)
            smax = fmaxf(smax, __shfl_xor_sync(FULLM, smax, off));

        bool iadm = h > smax;
        unsigned adm = __ballot_sync(FULLM, iadm);
        int cnt = __popc(adm);
        int need = KNN - done;

        if (cnt <= need) {
            int pos = done + __popc(adm & ((1u << lane) - 1u));
            if (iadm) {
                out[(size_t)r*KNN + pos] = tk_col<MODE>(hs, lane);
                h = s; hs = ss;         // promote
            }
            done += cnt;
        } else {
            // final fill: sort heads, take exactly `need` largest
            float hh = h;
            int   sl = lane;
            #pragma unroll
            for (int k = 2; k <= 32; k <<= 1) {
                #pragma unroll
                for (int j = k >> 1; j > 0; j >>= 1) {
                    float oh = __shfl_xor_sync(FULLM, hh, j);
                    int   ol = __shfl_xor_sync(FULLM, sl, j);
                    bool up = ((lane & k) == 0);
                    bool oless = (oh < hh) || (oh == hh && ol < sl);
                    bool takeMin = (((lane & j) == 0) == up);
                    bool pick_o = (oless == takeMin);
                    hh = pick_o ? oh : hh;
                    sl = pick_o ? ol : sl;
                }
            }
            int di = 31 - lane;
            int hsl = __shfl_sync(FULLM, hs, sl);
            if (di < need) out[(size_t)r*KNN + done + di] = tk_col<MODE>(hsl, sl);
            done = KNN;
        }
    }
}

__global__ void __launch_bounds__(256)
topk_warp(const float* __restrict__ S, int* __restrict__ out) {
    int warp = threadIdx.x >> 5, lane = threadIdx.x & 31;
    int r = blockIdx.x * 8 + warp;
    const float4* row4 = (const float4*)(S + (size_t)r * NN);
    float v[32];
    #pragma unroll
    for (int jf = 0; jf < 8; jf++) {
        float4 q = row4[jf*32 + lane];
        v[jf*4+0] = q.x; v[jf*4+1] = q.y; v[jf*4+2] = q.z; v[jf*4+3] = q.w;
    }
    warp_topk20<1>(v, r, lane, out);
}

// stage 1 fused: float4 loads of x rows, MODE-1 column bijection
__global__ void __launch_bounds__(256)
score1_topk(const float* __restrict__ x, int* __restrict__ out) {
    int warp = threadIdx.x >> 5, lane = threadIdx.x & 31;
    int r = blockIdx.x * 8 + warp;
    int b = r >> 10, n = r & 1023;
    const float* xb = x + (size_t)b*3*NN;
    const float4* xr4 = (const float4*)xb;
    const float4* yr4 = (const float4*)(xb + NN);
    const float4* zr4 = (const float4*)(xb + 2*NN);
    float cx = xb[n], cy = xb[NN + n], cz = xb[2*NN + n];
    float v[32];
    #pragma unroll
    for (int jf = 0; jf < 8; jf++) {
        float4 xq = xr4[jf*32 + lane];
        float4 yq = yr4[jf*32 + lane];
        float4 zq = zr4[jf*32 + lane];
        float xs[4] = {xq.x, xq.y, xq.z, xq.w};
        float ys[4] = {yq.x, yq.y, yq.z, yq.w};
        float zs[4] = {zq.x, zq.y, zq.z, zq.w};
        #pragma unroll
        for (int e = 0; e < 4; e++) {
            float half = -0.5f * (xs[e]*xs[e] + ys[e]*ys[e] + zs[e]*zs[e]);
            v[jf*4 + e] = fmaf(cx, xs[e], fmaf(cy, ys[e], fmaf(cz, zs[e], half)));
        }
    }
    warp_topk20<1>(v, r, lane, out);
}

// -------- single gather pass: BN stats + per-(point,channel) max --------
// grid (128, BB) = 1024 blocks, 8 points/block, 256 threads.
// Points processed in pairs with hoisted loads (2x MLP); accumulation order
// per thread is unchanged (point ii fully, then ii+PP) -> bit-identical sums.
__global__ void __launch_bounds__(256)
stats_mm_edge(const float* __restrict__ P, int ldp,
              const float* __restrict__ Q, int ldq,
              const int* __restrict__ idx, int O, int oshift,
              float* __restrict__ part,
              float* __restrict__ Mx) {
    __shared__ int sIdx[8*KNN];
    __shared__ float red1[256], red2[256];
    int b = blockIdx.y, i0 = blockIdx.x * 8;
    for (int e = threadIdx.x; e < 8*KNN; e += 256)
        sIdx[e] = idx[(size_t)(b*NN + i0)*KNN + e];
    __syncthreads();
    int o  = threadIdx.x & (O-1);
    int pp = threadIdx.x >> oshift;
    int PP = 256 >> oshift;
    float s1 = 0.f, s2 = 0.f;
    // 8/PP iterations per thread is always even (PP in {1,2,4}) -> pair them
    for (int ii = pp; ii < 8; ii += 2*PP) {
        int i2 = ii + PP;
        int gi0 = b*NN + i0 + ii;
        int gi1 = b*NN + i0 + i2;
        float qv0 = Q[(size_t)gi0*ldq + o];
        float qv1 = Q[(size_t)gi1*ldq + o];
        float pv0[KNN], pv1[KNN];
        #pragma unroll
        for (int k = 0; k < KNN; k++)
            pv0[k] = P[(size_t)(b*NN + sIdx[ii*KNN + k])*ldp + o];
        #pragma unroll
        for (int k = 0; k < KNN; k++)
            pv1[k] = P[(size_t)(b*NN + sIdx[i2*KNN + k])*ldp + o];
        float mx0 = -1e30f, mx1 = -1e30f;
        #pragma unroll
        for (int k = 0; k < KNN; k++) {
            float v = pv0[k] + qv0;
            s1 += v; s2 += v*v;
            mx0 = fmaxf(mx0, v);
        }
        Mx[(size_t)gi0*O + o] = mx0;
        #pragma unroll
        for (int k = 0; k < KNN; k++) {
            float v = pv1[k] + qv1;
            s1 += v; s2 += v*v;
            mx1 = fmaxf(mx1, v);
        }
        Mx[(size_t)gi1*O + o] = mx1;
    }
    red1[threadIdx.x] = s1; red2[threadIdx.x] = s2;
    __syncthreads();
    if (pp == 0) {
        for (int p = 1; p < PP; p++) { s1 += red1[o + p*O]; s2 += red2[o + p*O]; }
        int grp = blockIdx.y * 128 + blockIdx.x;   // < 1024
        part[(size_t)grp*O + o]          = s1;
        part[(size_t)(1024 + grp)*O + o] = s2;
    }
}

// grid (128, BB), 512 threads, 8 points/block
__global__ void stats_plain(const float* __restrict__ P, float* __restrict__ part) {
    int b = blockIdx.y, i0 = blockIdx.x * 8;
    int o = threadIdx.x;  // 512
    float s1 = 0.f, s2 = 0.f;
    #pragma unroll
    for (int ii = 0; ii < 8; ii++) {
        float v = P[(size_t)(b*NN + i0 + ii)*512 + o];
        s1 += v; s2 += v*v;
    }
    int grp = blockIdx.y * 128 + blockIdx.x;
    part[(size_t)grp*512 + o]          = s1;
    part[(size_t)(1024 + grp)*512 + o] = s2;
}

// warp-per-channel reduction over 1024 groups. grid = O/8, block = 256.
__global__ void __launch_bounds__(256)
reduce_stats(int O, float cnt, const float* __restrict__ part,
             float* __restrict__ mean, float* __restrict__ istd) {
    int warp = threadIdx.x >> 5, lane = threadIdx.x & 31;
    int o = blockIdx.x*8 + warp;
    float s1 = 0.f, s2 = 0.f;
    #pragma unroll
    for (int g = lane; g < 1024; g += 32) {
        s1 += part[(size_t)g*O + o];
        s2 += part[(size_t)(1024 + g)*O + o];
    }
    #pragma unroll
    for (int off = 16; off; off >>= 1) {
        s1 += __shfl_down_sync(FULLM, s1, off);
        s2 += __shfl_down_sync(FULLM, s2, off);
    }
    if (lane == 0) {
        float m = s1 / cnt;
        float var = s2 / cnt - m*m;
        mean[o] = m;
        istd[o] = rsqrtf(var + EPS);
    }
}

// -------- vectorized finalize from max (monotone BN+lrelu, scale>=0) --------
__global__ void __launch_bounds__(256)
finalize_mm4(const float4* __restrict__ Mx,
             int O, int oshift, int choff,
             const float4* __restrict__ ga, const float4* __restrict__ be,
             const float4* __restrict__ mean, const float4* __restrict__ istd,
             float* __restrict__ XCAT) {
    int t4 = blockIdx.x*256 + threadIdx.x;
    int gi = t4 >> (oshift - 2);
    int oq = t4 & ((O >> 2) - 1);
    float4 m = mean[oq], is = istd[oq], g = ga[oq], b = be[oq];
    float4 mx = Mx[t4];
    float4 r;
    {
        float sc = is.x * g.x;
        float z = (mx.x - m.x)*sc + b.x; r.x = (z >= 0.f) ? z : NEG*z;
    }
    {
        float sc = is.y * g.y;
        float z = (mx.y - m.y)*sc + b.y; r.y = (z >= 0.f) ? z : NEG*z;
    }
    {
        float sc = is.z * g.z;
        float z = (mx.z - m.z)*sc + b.z; r.z = (z >= 0.f) ? z : NEG*z;
    }
    {
        float sc = is.w * g.w;
        float z = (mx.w - m.w)*sc + b.w; r.w = (z >= 0.f) ? z : NEG*z;
    }
    *(float4*)&XCAT[(size_t)gi*512 + choff + oq*4] = r;
}

// -------- final BN+lrelu with transposed write to d_out (B,512,N) --------
__global__ void finalize5(const float* __restrict__ P,
                          const float* __restrict__ ga, const float* __restrict__ be,
                          const float* __restrict__ mean, const float* __restrict__ istd,
                          float* __restrict__ out) {
    __shared__ float tile[32][33];
    int b = blockIdx.z, o0 = blockIdx.y * 32, n0 = blockIdx.x * 32;
    int tid = threadIdx.x;
    #pragma unroll
    for (int l = 0; l < 4; l++) {
        int e = tid + l*256;
        int nn = e >> 5, oo = e & 31;
        int o = o0 + oo;
        float v = P[(size_t)(b*NN + n0 + nn)*512 + o];
        v = (v - mean[o]) * istd[o] * ga[o] + be[o];
        v = (v >= 0.f) ? v : NEG*v;
        tile[oo][nn] = v;
    }
    __syncthreads();
    #pragma unroll
    for (int l = 0; l < 4; l++) {
        int e = tid + l*256;
        int oo = e >> 5, nn = e & 31;
        out[(size_t)b*512*NN + (size_t)(o0 + oo)*NN + n0 + nn] = tile[oo][nn];
    }
}

extern "C" void kernel_launch(void* const* d_in, const int* in_sizes, int n_in,
                              void* d_out, int out_size) {
    const float* x  = (const float*)d_in[0];
    const float* y  = (const float*)d_in[1];
    const float* w1 = (const float*)d_in[2];
    const float* w2 = (const float*)d_in[3];
    const float* w3 = (const float*)d_in[4];
    const float* w4 = (const float*)d_in[5];
    const float* w5 = (const float*)d_in[6];
    const float* g1 = (const float*)d_in[7];  const float* b1 = (const float*)d_in[8];
    const float* g2 = (const float*)d_in[9];  const float* b2 = (const float*)d_in[10];
    const float* g3 = (const float*)d_in[11]; const float* b3 = (const float*)d_in[12];
    const float* g4 = (const float*)d_in[13]; const float* b4 = (const float*)d_in[14];
    const float* g5 = (const float*)d_in[15]; const float* b5 = (const float*)d_in[16];
    float* out = (float*)d_out;

    float *yT, *ynT, *XCAT, *S, *P, *P5, *Q, *Wc, *part, *mean, *istd;
    int* idx;
    cudaGetSymbolAddress((void**)&yT,  g_yT);
    cudaGetSymbolAddress((void**)&ynT, g_ynT);
    cudaGetSymbolAddress((void**)&XCAT,g_XCAT);
    cudaGetSymbolAddress((void**)&S,   g_S);
    cudaGetSymbolAddress((void**)&P,   g_P);
    cudaGetSymbolAddress((void**)&P5,  g_P5);
    cudaGetSymbolAddress((void**)&Q,   g_Q);
    cudaGetSymbolAddress((void**)&Wc,  g_Wc);
    cudaGetSymbolAddress((void**)&idx, g_idx);
    cudaGetSymbolAddress((void**)&part,g_part);
    cudaGetSymbolAddress((void**)&mean,g_mean);
    cudaGetSymbolAddress((void**)&istd,g_istd);

    float* Mx = S;                 // S is free outside score/topk windows

    // fork-join side stream (host objects only; no device memory)
    cudaStream_t s1;
    cudaStreamCreateWithFlags(&s1, cudaStreamNonBlocking);
    cudaEvent_t evF, evP1, evP2, evP3, evQ4, evP5a, evF1, evF2, evF3;
    cudaEventCreateWithFlags(&evF,   cudaEventDisableTiming);
    cudaEventCreateWithFlags(&evP1,  cudaEventDisableTiming);
    cudaEventCreateWithFlags(&evP2,  cudaEventDisableTiming);
    cudaEventCreateWithFlags(&evP3,  cudaEventDisableTiming);
    cudaEventCreateWithFlags(&evQ4,  cudaEventDisableTiming);
    cudaEventCreateWithFlags(&evP5a, cudaEventDisableTiming);
    cudaEventCreateWithFlags(&evF1,  cudaEventDisableTiming);
    cudaEventCreateWithFlags(&evF2,  cudaEventDisableTiming);
    cudaEventCreateWithFlags(&evF3,  cudaEventDisableTiming);

    // fork
    cudaEventRecord(evF, 0);
    cudaStreamWaitEvent(s1, evF, 0);

    // side: y prep + weights + stage-1 P + EARLY stage-4 gathered operand
    prep_y<<<BN, 128, 0, s1>>>(y, yT, ynT);
    make_weights<<<226, 256, 0, s1>>>(w1, w2, w3, w4, Wc);
    pq1_kernel<<<BN*32/256, 256, 0, s1>>>(x, Wc, P);
    cudaEventRecord(evP1, s1);
    gemm128<<<dim3(2,64,1), 256, 0, s1>>>(128, 1, 0, 0, yT, 128, 0, w4, 256, 0, Q, 256, 0);

    // main: stage 1
    score1_topk<<<BN/8, 256>>>(x, idx);
    cudaStreamWaitEvent(0, evP1, 0);
    stats_mm_edge<<<dim3(128,8), 256>>>(P, 128, P+64, 128, idx, 64, 6, part, Mx);
    reduce_stats<<<8, 256>>>(64, 163840.f, part, mean, istd);
    finalize_mm4<<<BN*64/1024, 256>>>((float4*)Mx, 64, 6, 0,
        (const float4*)g1, (const float4*)b1, (const float4*)mean, (const float4*)istd, XCAT);
    cudaEventRecord(evF1, 0);

    // side: stage2 PQ gemm
    cudaStreamWaitEvent(s1, evF1, 0);
    gemm128<<<dim3(1,64,1), 256, 0, s1>>>(64, 1, 0, 0, XCAT, 512, 0, Wc+WS2, 64, 0, P, 128, 0);
    cudaEventRecord(evP2, s1);

    // main: stage 2
    gemm128<<<dim3(8,8,8), 256>>>(64, 1, 1, 0, XCAT, 512, NN*512, XCAT, 512, NN*512, S, NN, NN*NN);
    topk_warp<<<BN/8, 256>>>(S, idx);
    cudaStreamWaitEvent(0, evP2, 0);
    stats_mm_edge<<<dim3(128,8), 256>>>(P, 128, P+64, 128, idx, 64, 6, part, Mx);
    reduce_stats<<<8, 256>>>(64, 163840.f, part, mean, istd);
    finalize_mm4<<<BN*64/1024, 256>>>((float4*)Mx, 64, 6, 64,
        (const float4*)g2, (const float4*)b2, (const float4*)mean, (const float4*)istd, XCAT);
    cudaEventRecord(evF2, 0);

    // side: stage3 PQ gemm
    cudaStreamWaitEvent(s1, evF2, 0);
    gemm128<<<dim3(2,64,1), 256, 0, s1>>>(64, 1, 0, 0, XCAT + 64, 512, 0, Wc+WS3, 64, 0, P, 256, 0);
    cudaEventRecord(evP3, s1);

    // main: stage 3
    gemm128<<<dim3(8,8,8), 256>>>(64, 1, 1, 0, XCAT + 64, 512, NN*512, XCAT + 64, 512, NN*512, S, NN, NN*NN);
    topk_warp<<<BN/8, 256>>>(S, idx);
    cudaStreamWaitEvent(0, evP3, 0);
    stats_mm_edge<<<dim3(128,8), 256>>>(P, 256, P+128, 256, idx, 128, 7, part, Mx);
    reduce_stats<<<16, 256>>>(128, 163840.f, part, mean, istd);
    finalize_mm4<<<BN*128/1024, 256>>>((float4*)Mx, 128, 7, 128,
        (const float4*)g3, (const float4*)b3, (const float4*)mean, (const float4*)istd, XCAT);
    cudaEventRecord(evF3, 0);

    // side: stage4 center operand (Wc4 @ x3 -> P), then stage5 first K-half
    cudaStreamWaitEvent(s1, evF3, 0);
    gemm128<<<dim3(2,64,1), 256, 0, s1>>>(128, 1, 0, 0, XCAT + 128, 512, 0, Wc+WS4, 128, 0, P, 256, 0);
    cudaEventRecord(evQ4, s1);
    gemm128<<<dim3(4,64,1), 256, 0, s1>>>(256, 1, 0, 0, XCAT, 512, 0, w5, 512, 0, P5, 512, 0);
    cudaEventRecord(evP5a, s1);

    // main: stage 4 (gathered operand = Q [yT@w4], center operand = P [Wc4@x3])
    gemm128<<<dim3(8,8,8), 256>>>(128, 1, 0, 0, XCAT + 128, 512, NN*512, ynT, 128, NN*128,
                                  S, NN, NN*NN);
    topk_warp<<<BN/8, 256>>>(S, idx);
    cudaStreamWaitEvent(0, evQ4, 0);
    stats_mm_edge<<<dim3(128,8), 256>>>(Q, 256, P, 256, idx, 256, 8, part, Mx);
    reduce_stats<<<32, 256>>>(256, 163840.f, part, mean, istd);
    finalize_mm4<<<BN*256/1024, 256>>>((float4*)Mx, 256, 8, 256,
        (const float4*)g4, (const float4*)b4, (const float4*)mean, (const float4*)istd, XCAT);

    // main: stage 5 (second K-half accumulates onto side-computed first half)
    cudaStreamWaitEvent(0, evP5a, 0);
    gemm128<<<dim3(4,64,1), 256>>>(256, 1, 0, 1, XCAT + 256, 512, 0, w5 + 256, 512, 0, P5, 512, 0);
    stats_plain<<<dim3(128,8), 512>>>(P5, part);
    reduce_stats<<<64, 256>>>(512, 8192.f, part, mean, istd);
    finalize5<<<dim3(32,16,8), 256>>>(P5, g5, b5, mean, istd, out);
}